// round 13
// baseline (speedup 1.0000x reference)
#include <cuda_runtime.h>
#include <cstdint>

// ---------------------------------------------------------------------------
// StructureEmbeddingLayer  B=128, N=48, E=64, D=256, M=49
// ---------------------------------------------------------------------------

typedef unsigned long long U64;

// ---- packed f32x2 helpers (sm_100+) ----
__device__ __forceinline__ U64 f2pk(float lo, float hi) {
    U64 r;
    asm("mov.b64 %0, {%1, %2};" : "=l"(r)
        : "r"(__float_as_uint(lo)), "r"(__float_as_uint(hi)));
    return r;
}
__device__ __forceinline__ void f2un(U64 v, float& lo, float& hi) {
    unsigned a, b;
    asm("mov.b64 {%0, %1}, %2;" : "=r"(a), "=r"(b) : "l"(v));
    lo = __uint_as_float(a); hi = __uint_as_float(b);
}
__device__ __forceinline__ U64 f2dup(float x) { return f2pk(x, x); }
__device__ __forceinline__ U64 f2add(U64 a, U64 b) {
    U64 r; asm("add.rn.f32x2 %0, %1, %2;" : "=l"(r) : "l"(a), "l"(b)); return r;
}
__device__ __forceinline__ U64 f2mul(U64 a, U64 b) {
    U64 r; asm("mul.rn.f32x2 %0, %1, %2;" : "=l"(r) : "l"(a), "l"(b)); return r;
}
__device__ __forceinline__ U64 f2fma(U64 a, U64 b, U64 c) {
    U64 r; asm("fma.rn.f32x2 %0, %1, %2, %3;" : "=l"(r) : "l"(a), "l"(b), "l"(c)); return r;
}

__device__ __forceinline__ float warp_sum(float v) {
#pragma unroll
    for (int o = 16; o; o >>= 1) v += __shfl_xor_sync(0xffffffffu, v, o);
    return v;
}

// streaming 16B store (evict-first)
__device__ __forceinline__ void stcs2(void* p, U64 a, U64 b) {
    asm volatile("st.global.cs.v2.u64 [%0], {%1, %2};"
                 :: "l"(p), "l"(a), "l"(b) : "memory");
}

// ---- scratch (no cudaMalloc allowed) ----
__device__ float  g_hb   [8192 * 256];   // masked bond embedding  [B*E, D]
__device__ float  g_rev  [8192 * 256];   // hb @ W_rev + b_rev     [B*E, D]
__device__ float  g_tsc_c[44 * 256];     // row-centered table_sc
__device__ float  g_wsf_c[8 * 256];      // row-centered W_sf
__device__ float  g_bsf_c[256];          // centered b_sf
__device__ float  g_wp   [8 * 256];      // W' = centered W_sf * gamma_sf
__device__ float  g_bp   [256];          // b' = centered b_sf * gamma_sf
__device__ float  g_dotc [600];          // cross-slice dot tables (6 x 10 x 10)
__device__ float  g_norm [40];           // per-used-row squared norms
__device__ float  g_G    [64];           // W_c W_c^T (8x8)
__device__ float  g_v    [8];            // W_c . b_c
__device__ float  g_n0   [1];            // ||b_c||^2
__device__ float2 g_rs   [128 * 48 * 48];// per-pair (combo-as-int-bits, rs_p)
__device__ float  g_T    [10000 * 256];  // LN-applied cate row per combo (+bias)

// ===========================================================================
// Kernel 0: center rows of table_sc / W_sf / b_sf (makes LN means exactly 0)
// ===========================================================================
__global__ void __launch_bounds__(256) center_kernel(
    const float* __restrict__ tsc, const float* __restrict__ Wsf,
    const float* __restrict__ bsf)
{
    __shared__ float red[8];
    const int blk = blockIdx.x, t = threadIdx.x;
    const float* src; float* dst;
    if (blk < 44)      { src = tsc + blk * 256;        dst = g_tsc_c + blk * 256; }
    else if (blk < 52) { src = Wsf + (blk - 44) * 256; dst = g_wsf_c + (blk - 44) * 256; }
    else               { src = bsf;                    dst = g_bsf_c; }
    float v = __ldg(src + t);
    float s = warp_sum(v);
    if ((t & 31) == 0) red[t >> 5] = s;
    __syncthreads();
    float tot = 0.f;
#pragma unroll
    for (int k = 0; k < 8; k++) tot += red[k];
    dst[t] = v - tot * (1.0f / 256.0f);
}

// ===========================================================================
// Kernel 0a: pre-scale projection weights by gamma_sf
// ===========================================================================
__global__ void __launch_bounds__(256) prep2_kernel(const float* __restrict__ gsf)
{
    const int blk = blockIdx.x, t = threadIdx.x;
    const float gv = __ldg(gsf + t);
    if (blk < 8) g_wp[blk * 256 + t] = g_wsf_c[blk * 256 + t] * gv;
    else         g_bp[t]             = g_bsf_c[t] * gv;
}

// ===========================================================================
// Kernel 0b: dot products for precomputed variances.
// ===========================================================================
__global__ void __launch_bounds__(256) dots_kernel()
{
    const int job = blockIdx.x * 8 + (threadIdx.x >> 5);
    const int lane = threadIdx.x & 31;
    if (job >= 713) return;
    const float *v1, *v2; float* dst;
    if (job < 600) {
        int combo = job / 100, ij = job % 100, i = ij / 10, jj = ij % 10;
        int r1, r2;
        switch (combo) {
            case 0:  r1 = 1 + i;  r2 = 12 + jj; break;   // A,B
            case 1:  r1 = 23 + i; r2 = 34 + jj; break;   // C,D
            case 2:  r1 = 1 + i;  r2 = 23 + jj; break;   // A,C
            case 3:  r1 = 1 + i;  r2 = 34 + jj; break;   // A,D
            case 4:  r1 = 12 + i; r2 = 23 + jj; break;   // B,C
            default: r1 = 12 + i; r2 = 34 + jj; break;   // B,D
        }
        v1 = g_tsc_c + r1 * 256; v2 = g_tsc_c + r2 * 256; dst = g_dotc + job;
    } else if (job < 640) {
        int jn = job - 600;
        int row = (jn / 10) * 11 + 1 + (jn % 10);
        v1 = v2 = g_tsc_c + row * 256; dst = g_norm + jn;
    } else if (job < 704) {
        int i = (job - 640) >> 3, jj = (job - 640) & 7;
        v1 = g_wsf_c + i * 256; v2 = g_wsf_c + jj * 256; dst = g_G + (job - 640);
    } else if (job < 712) {
        v1 = g_wsf_c + (job - 704) * 256; v2 = g_bsf_c; dst = g_v + (job - 704);
    } else {
        v1 = v2 = g_bsf_c; dst = g_n0;
    }
    float s = 0.f;
#pragma unroll
    for (int k = lane; k < 256; k += 32) s += v1[k] * v2[k];
    s = warp_sum(s);
    if (lane == 0) *dst = s;
}

// ---- common: per-lane 8-float loads (d = {4L..4L+3} U {128+4L..128+4L+3}) ----
__device__ __forceinline__ void ld8(const float* __restrict__ p, int lane, U64 v[4]) {
    float4 a = __ldg((const float4*)p + lane);
    float4 b = __ldg((const float4*)p + 32 + lane);
    v[0] = f2pk(a.x, a.y); v[1] = f2pk(a.z, a.w);
    v[2] = f2pk(b.x, b.y); v[3] = f2pk(b.z, b.w);
}

// ===========================================================================
// Kernel 0c: per-combo LN-applied cate table T[combo][d]
//   Warp per (a,b,c) triple; loops the 10 d values (loads 3 rows once).
//   grid 250 x 128.
// ===========================================================================
__global__ void __launch_bounds__(128) tbl_kernel(
    const float* __restrict__ gsc_p, const float* __restrict__ bsc_p,
    const float* __restrict__ bsf_ln)
{
    __shared__ float sQ[600];
    const int t = threadIdx.x;
    for (int idx = t; idx < 600; idx += 128) {
        float val = g_dotc[idx] * 2.f;
        int combo = idx / 100, ij = idx % 100, i = ij / 10, jj = ij % 10;
        if (combo == 0)      val += g_norm[i]      + g_norm[10 + jj];
        else if (combo == 1) val += g_norm[20 + i] + g_norm[30 + jj];
        sQ[idx] = val;
    }
    __syncthreads();

    const int lane = t & 31;
    const int triple = blockIdx.x * 4 + (t >> 5);   // 0..999
    const int a  = triple / 100;
    const int bb = (triple / 10) % 10;
    const int cc = triple % 10;

    const float base = sQ[a * 10 + bb] + sQ[200 + a * 10 + cc] + sQ[400 + bb * 10 + cc];

    U64 gsc[4], bsum[4];
    ld8(gsc_p, lane, gsc);
    {
        U64 t1[4], t2[4];
        ld8(bsc_p, lane, t1);
        ld8(bsf_ln, lane, t2);
#pragma unroll
        for (int k = 0; k < 4; k++) bsum[k] = f2add(t1[k], t2[k]);
    }

    U64 s3[4], u0[4], u1[4];
    ld8(g_tsc_c + (a + 1)   * 256, lane, s3);
    ld8(g_tsc_c + (bb + 12) * 256, lane, u0);
    ld8(g_tsc_c + (cc + 23) * 256, lane, u1);
#pragma unroll
    for (int k = 0; k < 4; k++) s3[k] = f2add(s3[k], f2add(u0[k], u1[k]));

    float* dst = g_T + (size_t)triple * 10 * 256 + lane * 4;
    const float* q1 = sQ + 100 + cc * 10;
    const float* q3 = sQ + 300 + a * 10;
    const float* q5 = sQ + 500 + bb * 10;

#pragma unroll
    for (int dd = 0; dd < 10; dd++) {
        U64 d4[4];
        ld8(g_tsc_c + (dd + 34) * 256, lane, d4);
        const float sc = base + q1[dd] + q3[dd] + q5[dd];
        const float rs_c = rsqrtf(fmaf(sc, 1.0f / 256.0f, 1e-5f));
        const U64 rc = f2dup(rs_c);

        U64 o[4];
#pragma unroll
        for (int k = 0; k < 4; k++) {
            U64 c = f2add(s3[k], d4[k]);
            o[k] = f2fma(c, f2mul(gsc[k], rc), bsum[k]);
        }
        ulonglong2 w0; w0.x = o[0]; w0.y = o[1];
        ulonglong2 w1; w1.x = o[2]; w1.y = o[3];
        *(ulonglong2*)dst         = w0;
        *(ulonglong2*)(dst + 128) = w1;
        dst += 256;
    }
}

// ===========================================================================
// Kernel 0d: per-pair (combo, rs_p) pre-pass + virtual-edge border writes
// ===========================================================================
__global__ void __launch_bounds__(256) rs_ve_kernel(
    const int4* __restrict__ sfc, const float4* __restrict__ sff,
    const float4* __restrict__ vev, float4* __restrict__ out)
{
    __shared__ float sG[64], sv2[8];
    __shared__ float sn0;
    const int t = threadIdx.x;
    if (t < 64) sG[t] = g_G[t];
    if (t < 8)  sv2[t] = 2.f * g_v[t];
    if (t == 0) sn0 = g_n0[0];
    __syncthreads();

    const int TOT = 128 * 48 * 48;
    for (int q = blockIdx.x * 256 + t; q < TOT; q += gridDim.x * 256) {
        const int4   ci = __ldg(sfc + q);
        const float4 x0 = __ldg(sff + 2 * q);
        const float4 x1 = __ldg(sff + 2 * q + 1);
        const int combo = ((ci.x * 10 + ci.y) * 10 + ci.z) * 10 + ci.w;
        const float xv[8] = { x0.x, x0.y, x0.z, x0.w, x1.x, x1.y, x1.z, x1.w };
        float sp = sn0;
#pragma unroll
        for (int a = 0; a < 8; a++) {
            float y = sv2[a];
#pragma unroll
            for (int b = 0; b < 8; b++) y = fmaf(sG[a * 8 + b], xv[b], y);
            sp = fmaf(xv[a], y, sp);
        }
        float2 meta;
        meta.x = __int_as_float(combo);
        meta.y = rsqrtf(fmaf(sp, 1.0f / 256.0f, 1e-5f));
        g_rs[q] = meta;
    }

    // virtual-edge border fill (disjoint output region)
    const int vtot = 128 * 97 * 64;
    for (int v = blockIdx.x * 256 + t; v < vtot; v += gridDim.x * 256) {
        int d4 = v & 63;
        int r = v >> 6;
        int b = r / 97;
        int pos = r - b * 97;                  // 0..48: (0,j)   49..96: (i,0)
        size_t cell = (size_t)b * 2401 + (pos < 49 ? pos : (size_t)(pos - 48) * 49);
        out[cell * 64 + d4] = __ldg(vev + d4);
    }
}

// ===========================================================================
// Kernel 1: per-bond embedding hb — warp per 2 bonds (grid 1024 x 128)
// ===========================================================================
__global__ void __launch_bounds__(128) hb_kernel(
    const int*   __restrict__ bfc,   // [B,E,3]
    const float* __restrict__ bff,   // [B,E,4]
    const float* __restrict__ mask,  // [B,E]
    const float* __restrict__ tbc,   // [33,256]
    const float* __restrict__ g1p, const float* __restrict__ b1p,
    const float* __restrict__ Wbf,   // [4,256]
    const float* __restrict__ bbf,
    const float* __restrict__ g2p, const float* __restrict__ b2p)
{
    const int lane = threadIdx.x & 31;
    const int gw = blockIdx.x * 4 + (threadIdx.x >> 5);   // 0..4095
    const int be0 = gw * 2;

    U64 g1[4], b1[4], g2[4], b2[4], bb[4], w[4][4];
    ld8(g1p, lane, g1); ld8(b1p, lane, b1);
    ld8(g2p, lane, g2); ld8(b2p, lane, b2);
    ld8(bbf, lane, bb);
#pragma unroll
    for (int f = 0; f < 4; f++) ld8(Wbf + f * 256, lane, w[f]);

#pragma unroll
    for (int u = 0; u < 2; u++) {
        const int be = be0 + u;
        const int c0 = __ldg(bfc + be * 3 + 0) + 1;
        const int c1 = __ldg(bfc + be * 3 + 1) + 12;
        const int c2 = __ldg(bfc + be * 3 + 2) + 23;

        U64 xc[4], t0[4], t1[4];
        ld8(tbc + c0 * 256, lane, xc);
        ld8(tbc + c1 * 256, lane, t0);
        ld8(tbc + c2 * 256, lane, t1);
#pragma unroll
        for (int k = 0; k < 4; k++) xc[k] = f2add(xc[k], f2add(t0[k], t1[k]));

        const float4 xf = __ldg((const float4*)(bff + be * 4));
        U64 xp[4];
#pragma unroll
        for (int k = 0; k < 4; k++) xp[k] = bb[k];
        {
            U64 d0 = f2dup(xf.x), d1 = f2dup(xf.y), d2 = f2dup(xf.z), d3 = f2dup(xf.w);
#pragma unroll
            for (int k = 0; k < 4; k++) {
                xp[k] = f2fma(w[0][k], d0, xp[k]);
                xp[k] = f2fma(w[1][k], d1, xp[k]);
                xp[k] = f2fma(w[2][k], d2, xp[k]);
                xp[k] = f2fma(w[3][k], d3, xp[k]);
            }
        }

        U64 sC = f2add(f2add(xc[0], xc[1]), f2add(xc[2], xc[3]));
        U64 qC = f2fma(xc[0], xc[0], f2fma(xc[1], xc[1], f2fma(xc[2], xc[2], f2mul(xc[3], xc[3]))));
        U64 sP = f2add(f2add(xp[0], xp[1]), f2add(xp[2], xp[3]));
        U64 qP = f2fma(xp[0], xp[0], f2fma(xp[1], xp[1], f2fma(xp[2], xp[2], f2mul(xp[3], xp[3]))));
        float a0, a1, s_c, q_c, s_p, q_p;
        f2un(sC, a0, a1); s_c = a0 + a1;
        f2un(qC, a0, a1); q_c = a0 + a1;
        f2un(sP, a0, a1); s_p = a0 + a1;
        f2un(qP, a0, a1); q_p = a0 + a1;
#pragma unroll
        for (int o = 16; o; o >>= 1) {
            s_c += __shfl_xor_sync(0xffffffffu, s_c, o);
            q_c += __shfl_xor_sync(0xffffffffu, q_c, o);
            s_p += __shfl_xor_sync(0xffffffffu, s_p, o);
            q_p += __shfl_xor_sync(0xffffffffu, q_p, o);
        }
        const float muC = s_c * (1.0f / 256.0f);
        const float rsC = rsqrtf(fmaf(q_c, 1.0f / 256.0f, -muC * muC) + 1e-5f);
        const float muP = s_p * (1.0f / 256.0f);
        const float rsP = rsqrtf(fmaf(q_p, 1.0f / 256.0f, -muP * muP) + 1e-5f);

        const float mv = __ldg(mask + be);
        const U64 mk = f2dup(mv);
        const U64 nmC = f2dup(-muC), rC = f2dup(rsC);
        const U64 nmP = f2dup(-muP), rP = f2dup(rsP);

        float* dst = g_hb + be * 256 + lane * 4;
#pragma unroll
        for (int half = 0; half < 2; half++) {
            U64 rgC0 = f2mul(g1[2 * half], rC),     rgC1 = f2mul(g1[2 * half + 1], rC);
            U64 kC0  = f2fma(rgC0, nmC, b1[2 * half]), kC1 = f2fma(rgC1, nmC, b1[2 * half + 1]);
            U64 rgP0 = f2mul(g2[2 * half], rP),     rgP1 = f2mul(g2[2 * half + 1], rP);
            U64 kP0  = f2fma(rgP0, nmP, b2[2 * half]), kP1 = f2fma(rgP1, nmP, b2[2 * half + 1]);
            U64 o0 = f2add(f2fma(xc[2 * half], rgC0, kC0), f2fma(xp[2 * half], rgP0, kP0));
            U64 o1 = f2add(f2fma(xc[2 * half + 1], rgC1, kC1), f2fma(xp[2 * half + 1], rgP1, kP1));
            o0 = f2mul(o0, mk); o1 = f2mul(o1, mk);
            ulonglong2 wv; wv.x = o0; wv.y = o1;
            *(ulonglong2*)(dst + half * 128) = wv;
        }
    }
}

// ===========================================================================
// Kernel 2: g_rev = g_hb @ W_rev + b_rev   (8192x256 @ 256x256)
// ===========================================================================
__global__ void __launch_bounds__(256) rev_kernel(
    const float* __restrict__ Wrev,
    const float* __restrict__ brev)
{
    constexpr int RROWS = 16, RPAD = 20;
    __shared__ __align__(16) float As[256 * RPAD];

    const int row0 = blockIdx.x * RROWS;
    const int t = threadIdx.x;

    for (int idx = t; idx < 256 * RROWS; idx += 256) {
        int r = idx >> 8;
        int k = idx & 255;
        As[k * RPAD + r] = g_hb[(row0 + r) * 256 + k];
    }
    __syncthreads();

    U64 acc[8];
#pragma unroll
    for (int p = 0; p < 8; p++) acc[p] = 0ULL;

#pragma unroll 4
    for (int k = 0; k < 256; k++) {
        U64 wd = f2dup(__ldg(Wrev + k * 256 + t));
        const ulonglong2* ap = (const ulonglong2*)(As + k * RPAD);
#pragma unroll
        for (int q = 0; q < 4; q++) {
            ulonglong2 a = ap[q];
            acc[2 * q]     = f2fma(a.x, wd, acc[2 * q]);
            acc[2 * q + 1] = f2fma(a.y, wd, acc[2 * q + 1]);
        }
    }

    const float bv = __ldg(brev + t);
#pragma unroll
    for (int p = 0; p < 8; p++) {
        float lo, hi; f2un(acc[p], lo, hi);
        g_rev[(row0 + 2 * p)     * 256 + t] = lo + bv;
        g_rev[(row0 + 2 * p + 1) * 256 + t] = hi + bv;
    }
}

// ===========================================================================
// Kernel 3: interior fill — warp per pair, NO smem, NO cate math.
//   out = T[combo] + rs_p * (b' + W'^T x).  2-deep load pipeline:
//   meta prefetched 2 pairs ahead, sff/T 1 pair ahead. Streaming stores.
// ===========================================================================
__global__ void __launch_bounds__(128, 3) fill_kernel(
    const float4* __restrict__ sff,   // [B*48*48*2] float4
    float* __restrict__ out)
{
    const int lane = threadIdx.x & 31;
    const int warp = threadIdx.x >> 5;

    U64 wp[8][4], bp[4];
#pragma unroll
    for (int f = 0; f < 8; f++) ld8(g_wp + f * 256, lane, wp[f]);
    ld8(g_bp, lane, bp);

    const int TOT = 128 * 48 * 48;
    const int NW = gridDim.x * 4;
    const int gw = blockIdx.x * 4 + warp;
    const int chunk = (TOT + NW - 1) / NW;
    int q = gw * chunk;
    int qend = q + chunk; if (qend > TOT) qend = TOT;
    if (q >= qend) return;

    int b = q / 2304;
    int rem = q - b * 2304;
    int i = rem / 48;
    int j = rem - i * 48;
    float* dst = out + ((size_t)((b * 49 + i + 1) * 49 + (j + 1))) * 256 + lane * 4;

    const int lane4 = lane * 4;

    // ---- prologue: meta[q], meta[q+1], x[q], T[q] ----
    int qc1 = q + 1 < TOT ? q + 1 : TOT - 1;
    float2 m0 = __ldg((const float2*)g_rs + q);
    float2 m1 = __ldg((const float2*)g_rs + qc1);
    float4 xa = __ldg(sff + 2 * q);
    float4 xb = __ldg(sff + 2 * q + 1);
    const float* Tr0 = g_T + (size_t)__float_as_int(m0.x) * 256 + lane4;
    float4 T0a = __ldg((const float4*)Tr0);
    float4 T0b = __ldg((const float4*)(Tr0 + 128));

    while (q < qend) {
        const int qn = q + 1;
        const int qc2 = qn + 1 < TOT ? qn + 1 : TOT - 1;
        const int qcn = qn < TOT ? qn : TOT - 1;

        // prefetch: meta[q+2], x[q+1], T[q+1] (address from m1, already resident)
        float2 m2 = __ldg((const float2*)g_rs + qc2);
        float4 xna = __ldg(sff + 2 * qcn);
        float4 xnb = __ldg(sff + 2 * qcn + 1);
        const float* Tr1 = g_T + (size_t)__float_as_int(m1.x) * 256 + lane4;
        float4 T1a = __ldg((const float4*)Tr1);
        float4 T1b = __ldg((const float4*)(Tr1 + 128));

        // compute current pair
        U64 p0 = bp[0], p1 = bp[1], p2 = bp[2], p3 = bp[3];
        const float xv[8] = { xa.x, xa.y, xa.z, xa.w, xb.x, xb.y, xb.z, xb.w };
#pragma unroll
        for (int f = 0; f < 8; f++) {
            U64 xd = f2dup(xv[f]);
            p0 = f2fma(wp[f][0], xd, p0);
            p1 = f2fma(wp[f][1], xd, p1);
            p2 = f2fma(wp[f][2], xd, p2);
            p3 = f2fma(wp[f][3], xd, p3);
        }

        const U64 rp = f2dup(m0.y);
        U64 o0 = f2fma(p0, rp, f2pk(T0a.x, T0a.y));
        U64 o1 = f2fma(p1, rp, f2pk(T0a.z, T0a.w));
        U64 o2 = f2fma(p2, rp, f2pk(T0b.x, T0b.y));
        U64 o3 = f2fma(p3, rp, f2pk(T0b.z, T0b.w));

        stcs2(dst,       o0, o1);
        stcs2(dst + 128, o2, o3);

        // rotate pipeline
        m0 = m1; m1 = m2;
        xa = xna; xb = xnb;
        T0a = T1a; T0b = T1b;

        q = qn;
        dst += 256;
        if (++j == 48) {
            j = 0; dst += 256;
            if (++i == 48) { i = 0; dst += 49 * 256; }
        }
    }
}

// ===========================================================================
// Kernel 4: scatter-add bonds with vectorized red.global (v4.f32)
// ===========================================================================
__global__ void __launch_bounds__(128) scatter_kernel(
    const int* __restrict__ bidx,
    float* __restrict__ out)
{
    const int be = blockIdx.x;
    const int b = be >> 6, e = be & 63;
    const int t = threadIdx.x;
    const int d4 = t & 63;
    const bool fwd = t < 64;

    const int i0 = __ldg(bidx + (b * 2)     * 64 + e) + 1;
    const int i1 = __ldg(bidx + (b * 2 + 1) * 64 + e) + 1;

    const float4* src = (const float4*)(fwd ? g_hb : g_rev) + be * 64 + d4;
    const float4 v = *src;

    const size_t cell = fwd ? ((size_t)(b * 49 + i0) * 49 + i1)
                            : ((size_t)(b * 49 + i1) * 49 + i0);
    float* p = out + cell * 256 + d4 * 4;
    asm volatile("red.global.add.v4.f32 [%0], {%1, %2, %3, %4};"
                 :: "l"(p), "f"(v.x), "f"(v.y), "f"(v.z), "f"(v.w)
                 : "memory");
}

// ===========================================================================
extern "C" void kernel_launch(void* const* d_in, const int* in_sizes, int n_in,
                              void* d_out, int out_size)
{
    (void)in_sizes; (void)n_in; (void)out_size;

    const int*    bond_index = (const int*)   d_in[0];
    const int*    bfc        = (const int*)   d_in[1];
    const float*  bff        = (const float*) d_in[2];
    const float*  bmask      = (const float*) d_in[3];
    const int4*   sfc        = (const int4*)  d_in[4];
    const float4* sff        = (const float4*)d_in[5];
    const float*  tbc        = (const float*) d_in[6];
    const float*  ln_bc_g    = (const float*) d_in[7];
    const float*  ln_bc_b    = (const float*) d_in[8];
    const float*  W_bf       = (const float*) d_in[9];
    const float*  b_bf       = (const float*) d_in[10];
    const float*  ln_bf_g    = (const float*) d_in[11];
    const float*  ln_bf_b    = (const float*) d_in[12];
    const float*  tsc        = (const float*) d_in[13];
    const float*  ln_sc_g    = (const float*) d_in[14];
    const float*  ln_sc_b    = (const float*) d_in[15];
    const float*  W_sf       = (const float*) d_in[16];
    const float*  b_sf       = (const float*) d_in[17];
    const float*  ln_sf_g    = (const float*) d_in[18];
    const float*  ln_sf_b    = (const float*) d_in[19];
    const float*  ve         = (const float*) d_in[20];
    const float*  W_rev      = (const float*) d_in[21];
    const float*  b_rev      = (const float*) d_in[22];
    float* out = (float*)d_out;

    center_kernel<<<53, 256>>>(tsc, W_sf, b_sf);
    prep2_kernel<<<9, 256>>>(ln_sf_g);
    dots_kernel<<<90, 256>>>();
    tbl_kernel<<<250, 128>>>(ln_sc_g, ln_sc_b, ln_sf_b);
    rs_ve_kernel<<<1152, 256>>>(sfc, sff, (const float4*)ve, (float4*)out);
    hb_kernel<<<1024, 128>>>(bfc, bff, bmask, tbc, ln_bc_g, ln_bc_b,
                             W_bf, b_bf, ln_bf_g, ln_bf_b);
    rev_kernel<<<512, 256>>>(W_rev, b_rev);
    fill_kernel<<<444, 128>>>(sff, out);
    scatter_kernel<<<8192, 128>>>(bond_index, out);
}

// round 14
// speedup vs baseline: 1.0041x; 1.0041x over previous
#include <cuda_runtime.h>
#include <cstdint>

// ---------------------------------------------------------------------------
// StructureEmbeddingLayer  B=128, N=48, E=64, D=256, M=49
// ---------------------------------------------------------------------------

typedef unsigned long long U64;

// ---- packed f32x2 helpers (sm_100+) ----
__device__ __forceinline__ U64 f2pk(float lo, float hi) {
    U64 r;
    asm("mov.b64 %0, {%1, %2};" : "=l"(r)
        : "r"(__float_as_uint(lo)), "r"(__float_as_uint(hi)));
    return r;
}
__device__ __forceinline__ void f2un(U64 v, float& lo, float& hi) {
    unsigned a, b;
    asm("mov.b64 {%0, %1}, %2;" : "=r"(a), "=r"(b) : "l"(v));
    lo = __uint_as_float(a); hi = __uint_as_float(b);
}
__device__ __forceinline__ U64 f2dup(float x) { return f2pk(x, x); }
__device__ __forceinline__ U64 f2add(U64 a, U64 b) {
    U64 r; asm("add.rn.f32x2 %0, %1, %2;" : "=l"(r) : "l"(a), "l"(b)); return r;
}
__device__ __forceinline__ U64 f2mul(U64 a, U64 b) {
    U64 r; asm("mul.rn.f32x2 %0, %1, %2;" : "=l"(r) : "l"(a), "l"(b)); return r;
}
__device__ __forceinline__ U64 f2fma(U64 a, U64 b, U64 c) {
    U64 r; asm("fma.rn.f32x2 %0, %1, %2, %3;" : "=l"(r) : "l"(a), "l"(b), "l"(c)); return r;
}

__device__ __forceinline__ float warp_sum(float v) {
#pragma unroll
    for (int o = 16; o; o >>= 1) v += __shfl_xor_sync(0xffffffffu, v, o);
    return v;
}

// streaming 16B store (evict-first)
__device__ __forceinline__ void stcs2(void* p, U64 a, U64 b) {
    asm volatile("st.global.cs.v2.u64 [%0], {%1, %2};"
                 :: "l"(p), "l"(a), "l"(b) : "memory");
}

// ---- scratch (no cudaMalloc allowed) ----
__device__ float  g_hb   [8192 * 256];   // masked bond embedding  [B*E, D]
__device__ float  g_rev  [8192 * 256];   // hb @ W_rev + b_rev     [B*E, D]
__device__ float  g_tsc_c[44 * 256];     // row-centered table_sc
__device__ float  g_wsf_c[8 * 256];      // row-centered W_sf
__device__ float  g_bsf_c[256];          // centered b_sf
__device__ float  g_wp   [8 * 256];      // W' = centered W_sf * gamma_sf
__device__ float  g_bp   [256];          // b' = centered b_sf * gamma_sf
__device__ float  g_dotc [600];          // cross-slice dot tables (6 x 10 x 10)
__device__ float  g_norm [40];           // per-used-row squared norms
__device__ float  g_G    [64];           // W_c W_c^T (8x8)
__device__ float  g_v    [8];            // W_c . b_c
__device__ float  g_n0   [1];            // ||b_c||^2
__device__ float2 g_rs   [128 * 48 * 48];// per-pair (combo-as-int-bits, rs_p)
__device__ float  g_T    [10000 * 256];  // LN-applied cate row per combo (+bias)

// ---- per-lane loads ----
__device__ __forceinline__ void ld8(const float* __restrict__ p, int lane, U64 v[4]) {
    float4 a = __ldg((const float4*)p + lane);
    float4 b = __ldg((const float4*)p + 32 + lane);
    v[0] = f2pk(a.x, a.y); v[1] = f2pk(a.z, a.w);
    v[2] = f2pk(b.x, b.y); v[3] = f2pk(b.z, b.w);
}
__device__ __forceinline__ void ld4(const float* __restrict__ p, int dbase, U64 v[2]) {
    float4 a = __ldg((const float4*)(p + dbase));
    v[0] = f2pk(a.x, a.y); v[1] = f2pk(a.z, a.w);
}

// ===========================================================================
// Kernel 0: center rows of table_sc / W_sf / b_sf (makes LN means exactly 0)
// ===========================================================================
__global__ void __launch_bounds__(256) center_kernel(
    const float* __restrict__ tsc, const float* __restrict__ Wsf,
    const float* __restrict__ bsf)
{
    __shared__ float red[8];
    const int blk = blockIdx.x, t = threadIdx.x;
    const float* src; float* dst;
    if (blk < 44)      { src = tsc + blk * 256;        dst = g_tsc_c + blk * 256; }
    else if (blk < 52) { src = Wsf + (blk - 44) * 256; dst = g_wsf_c + (blk - 44) * 256; }
    else               { src = bsf;                    dst = g_bsf_c; }
    float v = __ldg(src + t);
    float s = warp_sum(v);
    if ((t & 31) == 0) red[t >> 5] = s;
    __syncthreads();
    float tot = 0.f;
#pragma unroll
    for (int k = 0; k < 8; k++) tot += red[k];
    dst[t] = v - tot * (1.0f / 256.0f);
}

// ===========================================================================
// Kernel 0a: pre-scale projection weights by gamma_sf
// ===========================================================================
__global__ void __launch_bounds__(256) prep2_kernel(const float* __restrict__ gsf)
{
    const int blk = blockIdx.x, t = threadIdx.x;
    const float gv = __ldg(gsf + t);
    if (blk < 8) g_wp[blk * 256 + t] = g_wsf_c[blk * 256 + t] * gv;
    else         g_bp[t]             = g_bsf_c[t] * gv;
}

// ===========================================================================
// Kernel 0b: dot products for precomputed variances.
// ===========================================================================
__global__ void __launch_bounds__(256) dots_kernel()
{
    const int job = blockIdx.x * 8 + (threadIdx.x >> 5);
    const int lane = threadIdx.x & 31;
    if (job >= 713) return;
    const float *v1, *v2; float* dst;
    if (job < 600) {
        int combo = job / 100, ij = job % 100, i = ij / 10, jj = ij % 10;
        int r1, r2;
        switch (combo) {
            case 0:  r1 = 1 + i;  r2 = 12 + jj; break;   // A,B
            case 1:  r1 = 23 + i; r2 = 34 + jj; break;   // C,D
            case 2:  r1 = 1 + i;  r2 = 23 + jj; break;   // A,C
            case 3:  r1 = 1 + i;  r2 = 34 + jj; break;   // A,D
            case 4:  r1 = 12 + i; r2 = 23 + jj; break;   // B,C
            default: r1 = 12 + i; r2 = 34 + jj; break;   // B,D
        }
        v1 = g_tsc_c + r1 * 256; v2 = g_tsc_c + r2 * 256; dst = g_dotc + job;
    } else if (job < 640) {
        int jn = job - 600;
        int row = (jn / 10) * 11 + 1 + (jn % 10);
        v1 = v2 = g_tsc_c + row * 256; dst = g_norm + jn;
    } else if (job < 704) {
        int i = (job - 640) >> 3, jj = (job - 640) & 7;
        v1 = g_wsf_c + i * 256; v2 = g_wsf_c + jj * 256; dst = g_G + (job - 640);
    } else if (job < 712) {
        v1 = g_wsf_c + (job - 704) * 256; v2 = g_bsf_c; dst = g_v + (job - 704);
    } else {
        v1 = v2 = g_bsf_c; dst = g_n0;
    }
    float s = 0.f;
#pragma unroll
    for (int k = lane; k < 256; k += 32) s += v1[k] * v2[k];
    s = warp_sum(s);
    if (lane == 0) *dst = s;
}

// ===========================================================================
// Kernel 0c: per-combo LN-applied cate table T[combo][d]
//   Warp per (triple, d-half): 2000 warp jobs, 256-thread blocks, grid 250.
// ===========================================================================
__global__ void __launch_bounds__(256) tbl_kernel(
    const float* __restrict__ gsc_p, const float* __restrict__ bsc_p,
    const float* __restrict__ bsf_ln)
{
    __shared__ float sQ[600];
    const int t = threadIdx.x;
    for (int idx = t; idx < 600; idx += 256) {
        float val = g_dotc[idx] * 2.f;
        int combo = idx / 100, ij = idx % 100, i = ij / 10, jj = ij % 10;
        if (combo == 0)      val += g_norm[i]      + g_norm[10 + jj];
        else if (combo == 1) val += g_norm[20 + i] + g_norm[30 + jj];
        sQ[idx] = val;
    }
    __syncthreads();

    const int lane = t & 31;
    const int job = blockIdx.x * 8 + (t >> 5);     // 0..1999
    const int triple = job >> 1;                    // 0..999
    const int dh = job & 1;                         // which 128-half of D
    const int a  = triple / 100;
    const int bb = (triple / 10) % 10;
    const int cc = triple % 10;
    const int dbase = dh * 128 + lane * 4;

    const float base = sQ[a * 10 + bb] + sQ[200 + a * 10 + cc] + sQ[400 + bb * 10 + cc];

    U64 gsc[2], bsum[2];
    ld4(gsc_p, dbase, gsc);
    {
        U64 t1[2], t2[2];
        ld4(bsc_p, dbase, t1);
        ld4(bsf_ln, dbase, t2);
        bsum[0] = f2add(t1[0], t2[0]);
        bsum[1] = f2add(t1[1], t2[1]);
    }

    U64 s3[2], u0[2], u1[2];
    ld4(g_tsc_c + (a + 1)   * 256, dbase, s3);
    ld4(g_tsc_c + (bb + 12) * 256, dbase, u0);
    ld4(g_tsc_c + (cc + 23) * 256, dbase, u1);
    s3[0] = f2add(s3[0], f2add(u0[0], u1[0]));
    s3[1] = f2add(s3[1], f2add(u0[1], u1[1]));

    float* dst = g_T + (size_t)triple * 10 * 256 + dbase;
    const float* q1 = sQ + 100 + cc * 10;
    const float* q3 = sQ + 300 + a * 10;
    const float* q5 = sQ + 500 + bb * 10;

#pragma unroll
    for (int dd = 0; dd < 10; dd++) {
        U64 d2v[2];
        ld4(g_tsc_c + (dd + 34) * 256, dbase, d2v);
        const float sc = base + q1[dd] + q3[dd] + q5[dd];
        const float rs_c = rsqrtf(fmaf(sc, 1.0f / 256.0f, 1e-5f));
        const U64 rc = f2dup(rs_c);

        U64 o0 = f2fma(f2add(s3[0], d2v[0]), f2mul(gsc[0], rc), bsum[0]);
        U64 o1 = f2fma(f2add(s3[1], d2v[1]), f2mul(gsc[1], rc), bsum[1]);
        ulonglong2 w; w.x = o0; w.y = o1;
        *(ulonglong2*)dst = w;
        dst += 256;
    }
}

// ===========================================================================
// Kernel 0d: per-pair (combo, rs_p) pre-pass + virtual-edge border writes
// ===========================================================================
__global__ void __launch_bounds__(256) rs_ve_kernel(
    const int4* __restrict__ sfc, const float4* __restrict__ sff,
    const float4* __restrict__ vev, float4* __restrict__ out)
{
    __shared__ float sG[64], sv2[8];
    __shared__ float sn0;
    const int t = threadIdx.x;
    if (t < 64) sG[t] = g_G[t];
    if (t < 8)  sv2[t] = 2.f * g_v[t];
    if (t == 0) sn0 = g_n0[0];
    __syncthreads();

    const int TOT = 128 * 48 * 48;
    for (int q = blockIdx.x * 256 + t; q < TOT; q += gridDim.x * 256) {
        const int4   ci = __ldg(sfc + q);
        const float4 x0 = __ldg(sff + 2 * q);
        const float4 x1 = __ldg(sff + 2 * q + 1);
        const int combo = ((ci.x * 10 + ci.y) * 10 + ci.z) * 10 + ci.w;
        const float xv[8] = { x0.x, x0.y, x0.z, x0.w, x1.x, x1.y, x1.z, x1.w };
        float sp = sn0;
#pragma unroll
        for (int a = 0; a < 8; a++) {
            float y = sv2[a];
#pragma unroll
            for (int b = 0; b < 8; b++) y = fmaf(sG[a * 8 + b], xv[b], y);
            sp = fmaf(xv[a], y, sp);
        }
        float2 meta;
        meta.x = __int_as_float(combo);
        meta.y = rsqrtf(fmaf(sp, 1.0f / 256.0f, 1e-5f));
        g_rs[q] = meta;
    }

    // virtual-edge border fill (disjoint output region)
    const int vtot = 128 * 97 * 64;
    for (int v = blockIdx.x * 256 + t; v < vtot; v += gridDim.x * 256) {
        int d4 = v & 63;
        int r = v >> 6;
        int b = r / 97;
        int pos = r - b * 97;                  // 0..48: (0,j)   49..96: (i,0)
        size_t cell = (size_t)b * 2401 + (pos < 49 ? pos : (size_t)(pos - 48) * 49);
        out[cell * 64 + d4] = __ldg(vev + d4);
    }
}

// ===========================================================================
// Kernel 1: per-bond embedding hb — warp per 2 bonds (grid 512 x 256)
// ===========================================================================
__global__ void __launch_bounds__(256) hb_kernel(
    const int*   __restrict__ bfc,   // [B,E,3]
    const float* __restrict__ bff,   // [B,E,4]
    const float* __restrict__ mask,  // [B,E]
    const float* __restrict__ tbc,   // [33,256]
    const float* __restrict__ g1p, const float* __restrict__ b1p,
    const float* __restrict__ Wbf,   // [4,256]
    const float* __restrict__ bbf,
    const float* __restrict__ g2p, const float* __restrict__ b2p)
{
    const int lane = threadIdx.x & 31;
    const int gw = blockIdx.x * 8 + (threadIdx.x >> 5);   // 0..4095
    const int be0 = gw * 2;

    U64 g1[4], b1[4], g2[4], b2[4], bb[4], w[4][4];
    ld8(g1p, lane, g1); ld8(b1p, lane, b1);
    ld8(g2p, lane, g2); ld8(b2p, lane, b2);
    ld8(bbf, lane, bb);
#pragma unroll
    for (int f = 0; f < 4; f++) ld8(Wbf + f * 256, lane, w[f]);

#pragma unroll
    for (int u = 0; u < 2; u++) {
        const int be = be0 + u;
        const int c0 = __ldg(bfc + be * 3 + 0) + 1;
        const int c1 = __ldg(bfc + be * 3 + 1) + 12;
        const int c2 = __ldg(bfc + be * 3 + 2) + 23;

        U64 xc[4], t0[4], t1[4];
        ld8(tbc + c0 * 256, lane, xc);
        ld8(tbc + c1 * 256, lane, t0);
        ld8(tbc + c2 * 256, lane, t1);
#pragma unroll
        for (int k = 0; k < 4; k++) xc[k] = f2add(xc[k], f2add(t0[k], t1[k]));

        const float4 xf = __ldg((const float4*)(bff + be * 4));
        U64 xp[4];
#pragma unroll
        for (int k = 0; k < 4; k++) xp[k] = bb[k];
        {
            U64 d0 = f2dup(xf.x), d1 = f2dup(xf.y), d2 = f2dup(xf.z), d3 = f2dup(xf.w);
#pragma unroll
            for (int k = 0; k < 4; k++) {
                xp[k] = f2fma(w[0][k], d0, xp[k]);
                xp[k] = f2fma(w[1][k], d1, xp[k]);
                xp[k] = f2fma(w[2][k], d2, xp[k]);
                xp[k] = f2fma(w[3][k], d3, xp[k]);
            }
        }

        U64 sC = f2add(f2add(xc[0], xc[1]), f2add(xc[2], xc[3]));
        U64 qC = f2fma(xc[0], xc[0], f2fma(xc[1], xc[1], f2fma(xc[2], xc[2], f2mul(xc[3], xc[3]))));
        U64 sP = f2add(f2add(xp[0], xp[1]), f2add(xp[2], xp[3]));
        U64 qP = f2fma(xp[0], xp[0], f2fma(xp[1], xp[1], f2fma(xp[2], xp[2], f2mul(xp[3], xp[3]))));
        float a0, a1, s_c, q_c, s_p, q_p;
        f2un(sC, a0, a1); s_c = a0 + a1;
        f2un(qC, a0, a1); q_c = a0 + a1;
        f2un(sP, a0, a1); s_p = a0 + a1;
        f2un(qP, a0, a1); q_p = a0 + a1;
#pragma unroll
        for (int o = 16; o; o >>= 1) {
            s_c += __shfl_xor_sync(0xffffffffu, s_c, o);
            q_c += __shfl_xor_sync(0xffffffffu, q_c, o);
            s_p += __shfl_xor_sync(0xffffffffu, s_p, o);
            q_p += __shfl_xor_sync(0xffffffffu, q_p, o);
        }
        const float muC = s_c * (1.0f / 256.0f);
        const float rsC = rsqrtf(fmaf(q_c, 1.0f / 256.0f, -muC * muC) + 1e-5f);
        const float muP = s_p * (1.0f / 256.0f);
        const float rsP = rsqrtf(fmaf(q_p, 1.0f / 256.0f, -muP * muP) + 1e-5f);

        const float mv = __ldg(mask + be);
        const U64 mk = f2dup(mv);
        const U64 nmC = f2dup(-muC), rC = f2dup(rsC);
        const U64 nmP = f2dup(-muP), rP = f2dup(rsP);

        float* dst = g_hb + be * 256 + lane * 4;
#pragma unroll
        for (int half = 0; half < 2; half++) {
            U64 rgC0 = f2mul(g1[2 * half], rC),     rgC1 = f2mul(g1[2 * half + 1], rC);
            U64 kC0  = f2fma(rgC0, nmC, b1[2 * half]), kC1 = f2fma(rgC1, nmC, b1[2 * half + 1]);
            U64 rgP0 = f2mul(g2[2 * half], rP),     rgP1 = f2mul(g2[2 * half + 1], rP);
            U64 kP0  = f2fma(rgP0, nmP, b2[2 * half]), kP1 = f2fma(rgP1, nmP, b2[2 * half + 1]);
            U64 o0 = f2add(f2fma(xc[2 * half], rgC0, kC0), f2fma(xp[2 * half], rgP0, kP0));
            U64 o1 = f2add(f2fma(xc[2 * half + 1], rgC1, kC1), f2fma(xp[2 * half + 1], rgP1, kP1));
            o0 = f2mul(o0, mk); o1 = f2mul(o1, mk);
            ulonglong2 wv; wv.x = o0; wv.y = o1;
            *(ulonglong2*)(dst + half * 128) = wv;
        }
    }
}

// ===========================================================================
// Fused kernel: even blocks -> rev GEMM, odd blocks -> interior fill.
//   rev (FMA-bound) hides under fill (LTS/DRAM-bound).
// ===========================================================================
__global__ void __launch_bounds__(256) revfill_kernel(
    const float*  __restrict__ Wrev,   // [256,256]
    const float*  __restrict__ brev,   // [256]
    const float4* __restrict__ sff,    // [B*48*48*2] float4
    float* __restrict__ out)
{
    __shared__ __align__(16) float As[256 * 20];
    const int t = threadIdx.x;

    if ((blockIdx.x & 1) == 0) {
        // ---------------- rev: 16 rows of g_hb @ W_rev ----------------
        const int row0 = (blockIdx.x >> 1) * 16;
        constexpr int RPAD = 20;

        for (int idx = t; idx < 256 * 16; idx += 256) {
            int r = idx >> 8;
            int k = idx & 255;
            As[k * RPAD + r] = g_hb[(row0 + r) * 256 + k];
        }
        __syncthreads();

        U64 acc[8];
#pragma unroll
        for (int p = 0; p < 8; p++) acc[p] = 0ULL;

#pragma unroll 4
        for (int k = 0; k < 256; k++) {
            U64 wd = f2dup(__ldg(Wrev + k * 256 + t));
            const ulonglong2* ap = (const ulonglong2*)(As + k * RPAD);
#pragma unroll
            for (int q = 0; q < 4; q++) {
                ulonglong2 a = ap[q];
                acc[2 * q]     = f2fma(a.x, wd, acc[2 * q]);
                acc[2 * q + 1] = f2fma(a.y, wd, acc[2 * q + 1]);
            }
        }

        const float bv = __ldg(brev + t);
#pragma unroll
        for (int p = 0; p < 8; p++) {
            float lo, hi; f2un(acc[p], lo, hi);
            g_rev[(row0 + 2 * p)     * 256 + t] = lo + bv;
            g_rev[(row0 + 2 * p + 1) * 256 + t] = hi + bv;
        }
    } else {
        // ---------------- fill: 8 warps, warp per pair-chunk ----------------
        const int lane = t & 31;
        const int warp = t >> 5;
        const int fid = blockIdx.x >> 1;               // 0..511

        U64 wp[8][4], bp[4];
#pragma unroll
        for (int f = 0; f < 8; f++) ld8(g_wp + f * 256, lane, wp[f]);
        ld8(g_bp, lane, bp);

        const int TOT = 128 * 48 * 48;                 // 294912
        const int NW = 512 * 8;                        // 4096 warps
        const int gw = fid * 8 + warp;
        const int chunk = TOT / NW;                    // 72 exactly
        int q = gw * chunk;
        const int qend = q + chunk;

        int b = q / 2304;
        int rem = q - b * 2304;
        int i = rem / 48;
        int j = rem - i * 48;
        float* dst = out + ((size_t)((b * 49 + i + 1) * 49 + (j + 1))) * 256 + lane * 4;
        const int lane4 = lane * 4;

        while (q < qend) {
            const float2 meta = __ldg((const float2*)g_rs + q);
            const int combo = __float_as_int(meta.x);
            const float4 x0 = __ldg(sff + 2 * q);
            const float4 x1 = __ldg(sff + 2 * q + 1);

            const float* Tr = g_T + (size_t)combo * 256 + lane4;
            const float4 t0 = __ldg((const float4*)Tr);
            const float4 t1 = __ldg((const float4*)(Tr + 128));

            U64 p0 = bp[0], p1 = bp[1], p2 = bp[2], p3 = bp[3];
            const float xv[8] = { x0.x, x0.y, x0.z, x0.w, x1.x, x1.y, x1.z, x1.w };
#pragma unroll
            for (int f = 0; f < 8; f++) {
                U64 xd = f2dup(xv[f]);
                p0 = f2fma(wp[f][0], xd, p0);
                p1 = f2fma(wp[f][1], xd, p1);
                p2 = f2fma(wp[f][2], xd, p2);
                p3 = f2fma(wp[f][3], xd, p3);
            }

            const U64 rp = f2dup(meta.y);
            U64 o0 = f2fma(p0, rp, f2pk(t0.x, t0.y));
            U64 o1 = f2fma(p1, rp, f2pk(t0.z, t0.w));
            U64 o2 = f2fma(p2, rp, f2pk(t1.x, t1.y));
            U64 o3 = f2fma(p3, rp, f2pk(t1.z, t1.w));

            stcs2(dst,       o0, o1);
            stcs2(dst + 128, o2, o3);

            q++;
            dst += 256;
            if (++j == 48) {
                j = 0; dst += 256;
                if (++i == 48) { i = 0; dst += 49 * 256; }
            }
        }
    }
}

// ===========================================================================
// Kernel 4: scatter-add bonds with vectorized red.global (v4.f32)
// ===========================================================================
__global__ void __launch_bounds__(128) scatter_kernel(
    const int* __restrict__ bidx,
    float* __restrict__ out)
{
    const int be = blockIdx.x;
    const int b = be >> 6, e = be & 63;
    const int t = threadIdx.x;
    const int d4 = t & 63;
    const bool fwd = t < 64;

    const int i0 = __ldg(bidx + (b * 2)     * 64 + e) + 1;
    const int i1 = __ldg(bidx + (b * 2 + 1) * 64 + e) + 1;

    const float4* src = (const float4*)(fwd ? g_hb : g_rev) + be * 64 + d4;
    const float4 v = *src;

    const size_t cell = fwd ? ((size_t)(b * 49 + i0) * 49 + i1)
                            : ((size_t)(b * 49 + i1) * 49 + i0);
    float* p = out + cell * 256 + d4 * 4;
    asm volatile("red.global.add.v4.f32 [%0], {%1, %2, %3, %4};"
                 :: "l"(p), "f"(v.x), "f"(v.y), "f"(v.z), "f"(v.w)
                 : "memory");
}

// ===========================================================================
extern "C" void kernel_launch(void* const* d_in, const int* in_sizes, int n_in,
                              void* d_out, int out_size)
{
    (void)in_sizes; (void)n_in; (void)out_size;

    const int*    bond_index = (const int*)   d_in[0];
    const int*    bfc        = (const int*)   d_in[1];
    const float*  bff        = (const float*) d_in[2];
    const float*  bmask      = (const float*) d_in[3];
    const int4*   sfc        = (const int4*)  d_in[4];
    const float4* sff        = (const float4*)d_in[5];
    const float*  tbc        = (const float*) d_in[6];
    const float*  ln_bc_g    = (const float*) d_in[7];
    const float*  ln_bc_b    = (const float*) d_in[8];
    const float*  W_bf       = (const float*) d_in[9];
    const float*  b_bf       = (const float*) d_in[10];
    const float*  ln_bf_g    = (const float*) d_in[11];
    const float*  ln_bf_b    = (const float*) d_in[12];
    const float*  tsc        = (const float*) d_in[13];
    const float*  ln_sc_g    = (const float*) d_in[14];
    const float*  ln_sc_b    = (const float*) d_in[15];
    const float*  W_sf       = (const float*) d_in[16];
    const float*  b_sf       = (const float*) d_in[17];
    const float*  ln_sf_g    = (const float*) d_in[18];
    const float*  ln_sf_b    = (const float*) d_in[19];
    const float*  ve         = (const float*) d_in[20];
    const float*  W_rev      = (const float*) d_in[21];
    const float*  b_rev      = (const float*) d_in[22];
    float* out = (float*)d_out;

    center_kernel<<<53, 256>>>(tsc, W_sf, b_sf);
    dots_kernel<<<90, 256>>>();
    prep2_kernel<<<9, 256>>>(ln_sf_g);
    tbl_kernel<<<250, 256>>>(ln_sc_g, ln_sc_b, ln_sf_b);
    rs_ve_kernel<<<1152, 256>>>(sfc, sff, (const float4*)ve, (float4*)out);
    hb_kernel<<<512, 256>>>(bfc, bff, bmask, tbc, ln_bc_g, ln_bc_b,
                            W_bf, b_bf, ln_bf_g, ln_bf_b);
    revfill_kernel<<<1024, 256>>>(W_rev, b_rev, sff, out);
    scatter_kernel<<<8192, 128>>>(bond_index, out);
}

// round 15
// speedup vs baseline: 1.0198x; 1.0156x over previous
#include <cuda_runtime.h>
#include <cuda_fp16.h>
#include <cstdint>

// ---------------------------------------------------------------------------
// StructureEmbeddingLayer  B=128, N=48, E=64, D=256, M=49
// ---------------------------------------------------------------------------

typedef unsigned long long U64;

// ---- packed f32x2 helpers (sm_100+) ----
__device__ __forceinline__ U64 f2pk(float lo, float hi) {
    U64 r;
    asm("mov.b64 %0, {%1, %2};" : "=l"(r)
        : "r"(__float_as_uint(lo)), "r"(__float_as_uint(hi)));
    return r;
}
__device__ __forceinline__ void f2un(U64 v, float& lo, float& hi) {
    unsigned a, b;
    asm("mov.b64 {%0, %1}, %2;" : "=r"(a), "=r"(b) : "l"(v));
    lo = __uint_as_float(a); hi = __uint_as_float(b);
}
__device__ __forceinline__ U64 f2dup(float x) { return f2pk(x, x); }
__device__ __forceinline__ U64 f2add(U64 a, U64 b) {
    U64 r; asm("add.rn.f32x2 %0, %1, %2;" : "=l"(r) : "l"(a), "l"(b)); return r;
}
__device__ __forceinline__ U64 f2mul(U64 a, U64 b) {
    U64 r; asm("mul.rn.f32x2 %0, %1, %2;" : "=l"(r) : "l"(a), "l"(b)); return r;
}
__device__ __forceinline__ U64 f2fma(U64 a, U64 b, U64 c) {
    U64 r; asm("fma.rn.f32x2 %0, %1, %2, %3;" : "=l"(r) : "l"(a), "l"(b), "l"(c)); return r;
}

__device__ __forceinline__ float warp_sum(float v) {
#pragma unroll
    for (int o = 16; o; o >>= 1) v += __shfl_xor_sync(0xffffffffu, v, o);
    return v;
}

// streaming 16B store (evict-first)
__device__ __forceinline__ void stcs2(void* p, U64 a, U64 b) {
    asm volatile("st.global.cs.v2.u64 [%0], {%1, %2};"
                 :: "l"(p), "l"(a), "l"(b) : "memory");
}

// ---- scratch (no cudaMalloc allowed) ----
__device__ float  g_hb   [8192 * 256];   // masked bond embedding  [B*E, D]
__device__ float  g_rev  [8192 * 256];   // hb @ W_rev + b_rev     [B*E, D]
__device__ float  g_tsc_c[44 * 256];     // row-centered table_sc
__device__ float  g_wsf_c[8 * 256];      // row-centered W_sf
__device__ float  g_bsf_c[256];          // centered b_sf
__device__ float  g_wp   [8 * 256];      // W' = centered W_sf * gamma_sf
__device__ float  g_bp   [256];          // b' = centered b_sf * gamma_sf
__device__ float  g_dotc [600];          // cross-slice dot tables (6 x 10 x 10)
__device__ float  g_norm [40];           // per-used-row squared norms
__device__ float  g_G    [64];           // W_c W_c^T (8x8)
__device__ float  g_v    [8];            // W_c . b_c
__device__ float  g_n0   [1];            // ||b_c||^2
__device__ float2 g_rs   [128 * 48 * 48];// per-pair (combo-as-int-bits, rs_p)
__device__ __half g_Th   [10000 * 256];  // fp16 LN-applied cate row per combo (+bias)

// ---- per-lane loads ----
__device__ __forceinline__ void ld8(const float* __restrict__ p, int lane, U64 v[4]) {
    float4 a = __ldg((const float4*)p + lane);
    float4 b = __ldg((const float4*)p + 32 + lane);
    v[0] = f2pk(a.x, a.y); v[1] = f2pk(a.z, a.w);
    v[2] = f2pk(b.x, b.y); v[3] = f2pk(b.z, b.w);
}
__device__ __forceinline__ void ld4(const float* __restrict__ p, int dbase, U64 v[2]) {
    float4 a = __ldg((const float4*)(p + dbase));
    v[0] = f2pk(a.x, a.y); v[1] = f2pk(a.z, a.w);
}

// ===========================================================================
// Kernel 0: center rows of table_sc / W_sf / b_sf (makes LN means exactly 0)
// ===========================================================================
__global__ void __launch_bounds__(256) center_kernel(
    const float* __restrict__ tsc, const float* __restrict__ Wsf,
    const float* __restrict__ bsf)
{
    __shared__ float red[8];
    const int blk = blockIdx.x, t = threadIdx.x;
    const float* src; float* dst;
    if (blk < 44)      { src = tsc + blk * 256;        dst = g_tsc_c + blk * 256; }
    else if (blk < 52) { src = Wsf + (blk - 44) * 256; dst = g_wsf_c + (blk - 44) * 256; }
    else               { src = bsf;                    dst = g_bsf_c; }
    float v = __ldg(src + t);
    float s = warp_sum(v);
    if ((t & 31) == 0) red[t >> 5] = s;
    __syncthreads();
    float tot = 0.f;
#pragma unroll
    for (int k = 0; k < 8; k++) tot += red[k];
    dst[t] = v - tot * (1.0f / 256.0f);
}

// ===========================================================================
// Kernel 0a: pre-scale projection weights by gamma_sf
// ===========================================================================
__global__ void __launch_bounds__(256) prep2_kernel(const float* __restrict__ gsf)
{
    const int blk = blockIdx.x, t = threadIdx.x;
    const float gv = __ldg(gsf + t);
    if (blk < 8) g_wp[blk * 256 + t] = g_wsf_c[blk * 256 + t] * gv;
    else         g_bp[t]             = g_bsf_c[t] * gv;
}

// ===========================================================================
// Kernel 0b: dot products for precomputed variances.
// ===========================================================================
__global__ void __launch_bounds__(256) dots_kernel()
{
    const int job = blockIdx.x * 8 + (threadIdx.x >> 5);
    const int lane = threadIdx.x & 31;
    if (job >= 713) return;
    const float *v1, *v2; float* dst;
    if (job < 600) {
        int combo = job / 100, ij = job % 100, i = ij / 10, jj = ij % 10;
        int r1, r2;
        switch (combo) {
            case 0:  r1 = 1 + i;  r2 = 12 + jj; break;   // A,B
            case 1:  r1 = 23 + i; r2 = 34 + jj; break;   // C,D
            case 2:  r1 = 1 + i;  r2 = 23 + jj; break;   // A,C
            case 3:  r1 = 1 + i;  r2 = 34 + jj; break;   // A,D
            case 4:  r1 = 12 + i; r2 = 23 + jj; break;   // B,C
            default: r1 = 12 + i; r2 = 34 + jj; break;   // B,D
        }
        v1 = g_tsc_c + r1 * 256; v2 = g_tsc_c + r2 * 256; dst = g_dotc + job;
    } else if (job < 640) {
        int jn = job - 600;
        int row = (jn / 10) * 11 + 1 + (jn % 10);
        v1 = v2 = g_tsc_c + row * 256; dst = g_norm + jn;
    } else if (job < 704) {
        int i = (job - 640) >> 3, jj = (job - 640) & 7;
        v1 = g_wsf_c + i * 256; v2 = g_wsf_c + jj * 256; dst = g_G + (job - 640);
    } else if (job < 712) {
        v1 = g_wsf_c + (job - 704) * 256; v2 = g_bsf_c; dst = g_v + (job - 704);
    } else {
        v1 = v2 = g_bsf_c; dst = g_n0;
    }
    float s = 0.f;
#pragma unroll
    for (int k = lane; k < 256; k += 32) s += v1[k] * v2[k];
    s = warp_sum(s);
    if (lane == 0) *dst = s;
}

// ===========================================================================
// Kernel 0c: per-combo LN-applied cate table T[combo][d] in fp16.
//   Warp per (triple, d-half, dd-half): 4000 warp jobs, grid 500 x 256.
// ===========================================================================
__global__ void __launch_bounds__(256) tbl_kernel(
    const float* __restrict__ gsc_p, const float* __restrict__ bsc_p,
    const float* __restrict__ bsf_ln)
{
    __shared__ float sQ[600];
    const int t = threadIdx.x;
    for (int idx = t; idx < 600; idx += 256) {
        float val = g_dotc[idx] * 2.f;
        int combo = idx / 100, ij = idx % 100, i = ij / 10, jj = ij % 10;
        if (combo == 0)      val += g_norm[i]      + g_norm[10 + jj];
        else if (combo == 1) val += g_norm[20 + i] + g_norm[30 + jj];
        sQ[idx] = val;
    }
    __syncthreads();

    const int lane = t & 31;
    const int job = blockIdx.x * 8 + (t >> 5);      // 0..3999
    const int triple = job >> 2;                     // 0..999
    const int dh  = (job >> 1) & 1;                  // 128-half of D
    const int ddh = job & 1;                         // dd in [5*ddh, 5*ddh+5)
    const int a  = triple / 100;
    const int bb = (triple / 10) % 10;
    const int cc = triple % 10;
    const int dbase = dh * 128 + lane * 4;

    const float base = sQ[a * 10 + bb] + sQ[200 + a * 10 + cc] + sQ[400 + bb * 10 + cc];

    U64 gsc[2], bsum[2];
    ld4(gsc_p, dbase, gsc);
    {
        U64 t1[2], t2[2];
        ld4(bsc_p, dbase, t1);
        ld4(bsf_ln, dbase, t2);
        bsum[0] = f2add(t1[0], t2[0]);
        bsum[1] = f2add(t1[1], t2[1]);
    }

    U64 s3[2], u0[2], u1[2];
    ld4(g_tsc_c + (a + 1)   * 256, dbase, s3);
    ld4(g_tsc_c + (bb + 12) * 256, dbase, u0);
    ld4(g_tsc_c + (cc + 23) * 256, dbase, u1);
    s3[0] = f2add(s3[0], f2add(u0[0], u1[0]));
    s3[1] = f2add(s3[1], f2add(u0[1], u1[1]));

    __half* dst = g_Th + (size_t)triple * 10 * 256 + (5 * ddh) * 256 + dbase;
    const float* q1 = sQ + 100 + cc * 10;
    const float* q3 = sQ + 300 + a * 10;
    const float* q5 = sQ + 500 + bb * 10;

#pragma unroll
    for (int k = 0; k < 5; k++) {
        const int dd = 5 * ddh + k;
        U64 d2v[2];
        ld4(g_tsc_c + (dd + 34) * 256, dbase, d2v);
        const float sc = base + q1[dd] + q3[dd] + q5[dd];
        const float rs_c = rsqrtf(fmaf(sc, 1.0f / 256.0f, 1e-5f));
        const U64 rc = f2dup(rs_c);

        U64 o0 = f2fma(f2add(s3[0], d2v[0]), f2mul(gsc[0], rc), bsum[0]);
        U64 o1 = f2fma(f2add(s3[1], d2v[1]), f2mul(gsc[1], rc), bsum[1]);
        float a0, a1, b0, b1;
        f2un(o0, a0, a1); f2un(o1, b0, b1);
        __half2 h0 = __floats2half2_rn(a0, a1);
        __half2 h1 = __floats2half2_rn(b0, b1);
        uint2 w;
        w.x = *(unsigned*)&h0;
        w.y = *(unsigned*)&h1;
        *(uint2*)dst = w;
        dst += 256;
    }
}

// ===========================================================================
// Kernel 0d: per-pair (combo, rs_p) pre-pass + virtual-edge border writes
// ===========================================================================
__global__ void __launch_bounds__(256) rs_ve_kernel(
    const int4* __restrict__ sfc, const float4* __restrict__ sff,
    const float4* __restrict__ vev, float4* __restrict__ out)
{
    __shared__ float sG[64], sv2[8];
    __shared__ float sn0;
    const int t = threadIdx.x;
    if (t < 64) sG[t] = g_G[t];
    if (t < 8)  sv2[t] = 2.f * g_v[t];
    if (t == 0) sn0 = g_n0[0];
    __syncthreads();

    const int TOT = 128 * 48 * 48;
    for (int q = blockIdx.x * 256 + t; q < TOT; q += gridDim.x * 256) {
        const int4   ci = __ldg(sfc + q);
        const float4 x0 = __ldg(sff + 2 * q);
        const float4 x1 = __ldg(sff + 2 * q + 1);
        const int combo = ((ci.x * 10 + ci.y) * 10 + ci.z) * 10 + ci.w;
        const float xv[8] = { x0.x, x0.y, x0.z, x0.w, x1.x, x1.y, x1.z, x1.w };
        float sp = sn0;
#pragma unroll
        for (int a = 0; a < 8; a++) {
            float y = sv2[a];
#pragma unroll
            for (int b = 0; b < 8; b++) y = fmaf(sG[a * 8 + b], xv[b], y);
            sp = fmaf(xv[a], y, sp);
        }
        float2 meta;
        meta.x = __int_as_float(combo);
        meta.y = rsqrtf(fmaf(sp, 1.0f / 256.0f, 1e-5f));
        g_rs[q] = meta;
    }

    // virtual-edge border fill (disjoint output region)
    const int vtot = 128 * 97 * 64;
    for (int v = blockIdx.x * 256 + t; v < vtot; v += gridDim.x * 256) {
        int d4 = v & 63;
        int r = v >> 6;
        int b = r / 97;
        int pos = r - b * 97;                  // 0..48: (0,j)   49..96: (i,0)
        size_t cell = (size_t)b * 2401 + (pos < 49 ? pos : (size_t)(pos - 48) * 49);
        out[cell * 64 + d4] = __ldg(vev + d4);
    }
}

// ===========================================================================
// Kernel 1: per-bond embedding hb — warp per 2 bonds (grid 512 x 256)
// ===========================================================================
__global__ void __launch_bounds__(256) hb_kernel(
    const int*   __restrict__ bfc,   // [B,E,3]
    const float* __restrict__ bff,   // [B,E,4]
    const float* __restrict__ mask,  // [B,E]
    const float* __restrict__ tbc,   // [33,256]
    const float* __restrict__ g1p, const float* __restrict__ b1p,
    const float* __restrict__ Wbf,   // [4,256]
    const float* __restrict__ bbf,
    const float* __restrict__ g2p, const float* __restrict__ b2p)
{
    const int lane = threadIdx.x & 31;
    const int gw = blockIdx.x * 8 + (threadIdx.x >> 5);   // 0..4095
    const int be0 = gw * 2;

    U64 g1[4], b1[4], g2[4], b2[4], bb[4], w[4][4];
    ld8(g1p, lane, g1); ld8(b1p, lane, b1);
    ld8(g2p, lane, g2); ld8(b2p, lane, b2);
    ld8(bbf, lane, bb);
#pragma unroll
    for (int f = 0; f < 4; f++) ld8(Wbf + f * 256, lane, w[f]);

#pragma unroll
    for (int u = 0; u < 2; u++) {
        const int be = be0 + u;
        const int c0 = __ldg(bfc + be * 3 + 0) + 1;
        const int c1 = __ldg(bfc + be * 3 + 1) + 12;
        const int c2 = __ldg(bfc + be * 3 + 2) + 23;

        U64 xc[4], t0[4], t1[4];
        ld8(tbc + c0 * 256, lane, xc);
        ld8(tbc + c1 * 256, lane, t0);
        ld8(tbc + c2 * 256, lane, t1);
#pragma unroll
        for (int k = 0; k < 4; k++) xc[k] = f2add(xc[k], f2add(t0[k], t1[k]));

        const float4 xf = __ldg((const float4*)(bff + be * 4));
        U64 xp[4];
#pragma unroll
        for (int k = 0; k < 4; k++) xp[k] = bb[k];
        {
            U64 d0 = f2dup(xf.x), d1 = f2dup(xf.y), d2 = f2dup(xf.z), d3 = f2dup(xf.w);
#pragma unroll
            for (int k = 0; k < 4; k++) {
                xp[k] = f2fma(w[0][k], d0, xp[k]);
                xp[k] = f2fma(w[1][k], d1, xp[k]);
                xp[k] = f2fma(w[2][k], d2, xp[k]);
                xp[k] = f2fma(w[3][k], d3, xp[k]);
            }
        }

        U64 sC = f2add(f2add(xc[0], xc[1]), f2add(xc[2], xc[3]));
        U64 qC = f2fma(xc[0], xc[0], f2fma(xc[1], xc[1], f2fma(xc[2], xc[2], f2mul(xc[3], xc[3]))));
        U64 sP = f2add(f2add(xp[0], xp[1]), f2add(xp[2], xp[3]));
        U64 qP = f2fma(xp[0], xp[0], f2fma(xp[1], xp[1], f2fma(xp[2], xp[2], f2mul(xp[3], xp[3]))));
        float a0, a1, s_c, q_c, s_p, q_p;
        f2un(sC, a0, a1); s_c = a0 + a1;
        f2un(qC, a0, a1); q_c = a0 + a1;
        f2un(sP, a0, a1); s_p = a0 + a1;
        f2un(qP, a0, a1); q_p = a0 + a1;
#pragma unroll
        for (int o = 16; o; o >>= 1) {
            s_c += __shfl_xor_sync(0xffffffffu, s_c, o);
            q_c += __shfl_xor_sync(0xffffffffu, q_c, o);
            s_p += __shfl_xor_sync(0xffffffffu, s_p, o);
            q_p += __shfl_xor_sync(0xffffffffu, q_p, o);
        }
        const float muC = s_c * (1.0f / 256.0f);
        const float rsC = rsqrtf(fmaf(q_c, 1.0f / 256.0f, -muC * muC) + 1e-5f);
        const float muP = s_p * (1.0f / 256.0f);
        const float rsP = rsqrtf(fmaf(q_p, 1.0f / 256.0f, -muP * muP) + 1e-5f);

        const float mv = __ldg(mask + be);
        const U64 mk = f2dup(mv);
        const U64 nmC = f2dup(-muC), rC = f2dup(rsC);
        const U64 nmP = f2dup(-muP), rP = f2dup(rsP);

        float* dst = g_hb + be * 256 + lane * 4;
#pragma unroll
        for (int half = 0; half < 2; half++) {
            U64 rgC0 = f2mul(g1[2 * half], rC),     rgC1 = f2mul(g1[2 * half + 1], rC);
            U64 kC0  = f2fma(rgC0, nmC, b1[2 * half]), kC1 = f2fma(rgC1, nmC, b1[2 * half + 1]);
            U64 rgP0 = f2mul(g2[2 * half], rP),     rgP1 = f2mul(g2[2 * half + 1], rP);
            U64 kP0  = f2fma(rgP0, nmP, b2[2 * half]), kP1 = f2fma(rgP1, nmP, b2[2 * half + 1]);
            U64 o0 = f2add(f2fma(xc[2 * half], rgC0, kC0), f2fma(xp[2 * half], rgP0, kP0));
            U64 o1 = f2add(f2fma(xc[2 * half + 1], rgC1, kC1), f2fma(xp[2 * half + 1], rgP1, kP1));
            o0 = f2mul(o0, mk); o1 = f2mul(o1, mk);
            ulonglong2 wv; wv.x = o0; wv.y = o1;
            *(ulonglong2*)(dst + half * 128) = wv;
        }
    }
}

// ===========================================================================
// Kernel 2: g_rev = g_hb @ W_rev + b_rev   (8192x256 @ 256x256)
// ===========================================================================
__global__ void __launch_bounds__(256) rev_kernel(
    const float* __restrict__ Wrev,
    const float* __restrict__ brev)
{
    constexpr int RROWS = 16, RPAD = 20;
    __shared__ __align__(16) float As[256 * RPAD];

    const int row0 = blockIdx.x * RROWS;
    const int t = threadIdx.x;

    for (int idx = t; idx < 256 * RROWS; idx += 256) {
        int r = idx >> 8;
        int k = idx & 255;
        As[k * RPAD + r] = g_hb[(row0 + r) * 256 + k];
    }
    __syncthreads();

    U64 acc[8];
#pragma unroll
    for (int p = 0; p < 8; p++) acc[p] = 0ULL;

#pragma unroll 4
    for (int k = 0; k < 256; k++) {
        U64 wd = f2dup(__ldg(Wrev + k * 256 + t));
        const ulonglong2* ap = (const ulonglong2*)(As + k * RPAD);
#pragma unroll
        for (int q = 0; q < 4; q++) {
            ulonglong2 a = ap[q];
            acc[2 * q]     = f2fma(a.x, wd, acc[2 * q]);
            acc[2 * q + 1] = f2fma(a.y, wd, acc[2 * q + 1]);
        }
    }

    const float bv = __ldg(brev + t);
#pragma unroll
    for (int p = 0; p < 8; p++) {
        float lo, hi; f2un(acc[p], lo, hi);
        g_rev[(row0 + 2 * p)     * 256 + t] = lo + bv;
        g_rev[(row0 + 2 * p + 1) * 256 + t] = hi + bv;
    }
}

// ===========================================================================
// Kernel 3: interior fill — warp per pair, T read as fp16 (half traffic).
//   out = float(Th[combo]) + rs_p * (b' + W'^T x).  Streaming stores.
// ===========================================================================
__global__ void __launch_bounds__(128, 4) fill_kernel(
    const float4* __restrict__ sff,   // [B*48*48*2] float4
    float* __restrict__ out)
{
    const int lane = threadIdx.x & 31;
    const int warp = threadIdx.x >> 5;

    U64 wp[8][4], bp[4];
#pragma unroll
    for (int f = 0; f < 8; f++) ld8(g_wp + f * 256, lane, wp[f]);
    ld8(g_bp, lane, bp);

    const int TOT = 128 * 48 * 48;
    const int NW = gridDim.x * 4;
    const int gw = blockIdx.x * 4 + warp;
    const int chunk = (TOT + NW - 1) / NW;
    int q = gw * chunk;
    int qend = q + chunk; if (qend > TOT) qend = TOT;
    if (q >= qend) return;

    int b = q / 2304;
    int rem = q - b * 2304;
    int i = rem / 48;
    int j = rem - i * 48;
    float* dst = out + ((size_t)((b * 49 + i + 1) * 49 + (j + 1))) * 256 + lane * 4;
    const int lane4 = lane * 4;

    while (q < qend) {
        const float2 meta = __ldg((const float2*)g_rs + q);
        const int combo = __float_as_int(meta.x);
        const float4 x0 = __ldg(sff + 2 * q);
        const float4 x1 = __ldg(sff + 2 * q + 1);

        const __half* Tr = g_Th + (size_t)combo * 256 + lane4;
        const uint2 ta = __ldg((const uint2*)Tr);          // halves 4L..4L+3
        const uint2 tb = __ldg((const uint2*)(Tr + 128));  // halves 128+4L..

        U64 p0 = bp[0], p1 = bp[1], p2 = bp[2], p3 = bp[3];
        const float xv[8] = { x0.x, x0.y, x0.z, x0.w, x1.x, x1.y, x1.z, x1.w };
#pragma unroll
        for (int f = 0; f < 8; f++) {
            U64 xd = f2dup(xv[f]);
            p0 = f2fma(wp[f][0], xd, p0);
            p1 = f2fma(wp[f][1], xd, p1);
            p2 = f2fma(wp[f][2], xd, p2);
            p3 = f2fma(wp[f][3], xd, p3);
        }

        const float2 f0 = __half22float2(*(const __half2*)&ta.x);
        const float2 f1 = __half22float2(*(const __half2*)&ta.y);
        const float2 f2_ = __half22float2(*(const __half2*)&tb.x);
        const float2 f3 = __half22float2(*(const __half2*)&tb.y);

        const U64 rp = f2dup(meta.y);
        U64 o0 = f2fma(p0, rp, f2pk(f0.x, f0.y));
        U64 o1 = f2fma(p1, rp, f2pk(f1.x, f1.y));
        U64 o2 = f2fma(p2, rp, f2pk(f2_.x, f2_.y));
        U64 o3 = f2fma(p3, rp, f2pk(f3.x, f3.y));

        stcs2(dst,       o0, o1);
        stcs2(dst + 128, o2, o3);

        q++;
        dst += 256;
        if (++j == 48) {
            j = 0; dst += 256;
            if (++i == 48) { i = 0; dst += 49 * 256; }
        }
    }
}

// ===========================================================================
// Kernel 4: scatter-add bonds with vectorized red.global (v4.f32)
// ===========================================================================
__global__ void __launch_bounds__(128) scatter_kernel(
    const int* __restrict__ bidx,
    float* __restrict__ out)
{
    const int be = blockIdx.x;
    const int b = be >> 6, e = be & 63;
    const int t = threadIdx.x;
    const int d4 = t & 63;
    const bool fwd = t < 64;

    const int i0 = __ldg(bidx + (b * 2)     * 64 + e) + 1;
    const int i1 = __ldg(bidx + (b * 2 + 1) * 64 + e) + 1;

    const float4* src = (const float4*)(fwd ? g_hb : g_rev) + be * 64 + d4;
    const float4 v = *src;

    const size_t cell = fwd ? ((size_t)(b * 49 + i0) * 49 + i1)
                            : ((size_t)(b * 49 + i1) * 49 + i0);
    float* p = out + cell * 256 + d4 * 4;
    asm volatile("red.global.add.v4.f32 [%0], {%1, %2, %3, %4};"
                 :: "l"(p), "f"(v.x), "f"(v.y), "f"(v.z), "f"(v.w)
                 : "memory");
}

// ===========================================================================
extern "C" void kernel_launch(void* const* d_in, const int* in_sizes, int n_in,
                              void* d_out, int out_size)
{
    (void)in_sizes; (void)n_in; (void)out_size;

    const int*    bond_index = (const int*)   d_in[0];
    const int*    bfc        = (const int*)   d_in[1];
    const float*  bff        = (const float*) d_in[2];
    const float*  bmask      = (const float*) d_in[3];
    const int4*   sfc        = (const int4*)  d_in[4];
    const float4* sff        = (const float4*)d_in[5];
    const float*  tbc        = (const float*) d_in[6];
    const float*  ln_bc_g    = (const float*) d_in[7];
    const float*  ln_bc_b    = (const float*) d_in[8];
    const float*  W_bf       = (const float*) d_in[9];
    const float*  b_bf       = (const float*) d_in[10];
    const float*  ln_bf_g    = (const float*) d_in[11];
    const float*  ln_bf_b    = (const float*) d_in[12];
    const float*  tsc        = (const float*) d_in[13];
    const float*  ln_sc_g    = (const float*) d_in[14];
    const float*  ln_sc_b    = (const float*) d_in[15];
    const float*  W_sf       = (const float*) d_in[16];
    const float*  b_sf       = (const float*) d_in[17];
    const float*  ln_sf_g    = (const float*) d_in[18];
    const float*  ln_sf_b    = (const float*) d_in[19];
    const float*  ve         = (const float*) d_in[20];
    const float*  W_rev      = (const float*) d_in[21];
    const float*  b_rev      = (const float*) d_in[22];
    float* out = (float*)d_out;

    center_kernel<<<53, 256>>>(tsc, W_sf, b_sf);
    dots_kernel<<<90, 256>>>();
    prep2_kernel<<<9, 256>>>(ln_sf_g);
    tbl_kernel<<<500, 256>>>(ln_sc_g, ln_sc_b, ln_sf_b);
    rs_ve_kernel<<<1152, 256>>>(sfc, sff, (const float4*)ve, (float4*)out);
    hb_kernel<<<512, 256>>>(bfc, bff, bmask, tbc, ln_bc_g, ln_bc_b,
                            W_bf, b_bf, ln_bf_g, ln_bf_b);
    rev_kernel<<<512, 256>>>(W_rev, b_rev);
    fill_kernel<<<444, 128>>>(sff, out);
    scatter_kernel<<<8192, 128>>>(bond_index, out);
}

// round 16
// speedup vs baseline: 1.1324x; 1.1105x over previous
#include <cuda_runtime.h>
#include <cuda_fp16.h>
#include <cstdint>

// ---------------------------------------------------------------------------
// StructureEmbeddingLayer  B=128, N=48, E=64, D=256, M=49
// ---------------------------------------------------------------------------

typedef unsigned long long U64;

// ---- packed f32x2 helpers (sm_100+) ----
__device__ __forceinline__ U64 f2pk(float lo, float hi) {
    U64 r;
    asm("mov.b64 %0, {%1, %2};" : "=l"(r)
        : "r"(__float_as_uint(lo)), "r"(__float_as_uint(hi)));
    return r;
}
__device__ __forceinline__ void f2un(U64 v, float& lo, float& hi) {
    unsigned a, b;
    asm("mov.b64 {%0, %1}, %2;" : "=r"(a), "=r"(b) : "l"(v));
    lo = __uint_as_float(a); hi = __uint_as_float(b);
}
__device__ __forceinline__ U64 f2dup(float x) { return f2pk(x, x); }
__device__ __forceinline__ U64 f2add(U64 a, U64 b) {
    U64 r; asm("add.rn.f32x2 %0, %1, %2;" : "=l"(r) : "l"(a), "l"(b)); return r;
}
__device__ __forceinline__ U64 f2mul(U64 a, U64 b) {
    U64 r; asm("mul.rn.f32x2 %0, %1, %2;" : "=l"(r) : "l"(a), "l"(b)); return r;
}
__device__ __forceinline__ U64 f2fma(U64 a, U64 b, U64 c) {
    U64 r; asm("fma.rn.f32x2 %0, %1, %2, %3;" : "=l"(r) : "l"(a), "l"(b), "l"(c)); return r;
}

__device__ __forceinline__ float warp_sum(float v) {
#pragma unroll
    for (int o = 16; o; o >>= 1) v += __shfl_xor_sync(0xffffffffu, v, o);
    return v;
}

// streaming 16B store (evict-first)
__device__ __forceinline__ void stcs2(void* p, U64 a, U64 b) {
    asm volatile("st.global.cs.v2.u64 [%0], {%1, %2};"
                 :: "l"(p), "l"(a), "l"(b) : "memory");
}

// ---- scratch (no cudaMalloc allowed) ----
__device__ float  g_hb   [8192 * 256];   // masked bond embedding  [B*E, D]
__device__ float  g_rev  [8192 * 256];   // hb @ W_rev + b_rev     [B*E, D]
__device__ float  g_tsc_c[44 * 256];     // row-centered table_sc
__device__ float  g_wsf_c[8 * 256];      // row-centered W_sf
__device__ float  g_bsf_c[256];          // centered b_sf
__device__ float  g_wp   [8 * 256];      // W' = centered W_sf * gamma_sf
__device__ float  g_bp   [256];          // b' = centered b_sf * gamma_sf
__device__ float  g_dotc [600];          // cross-slice dot tables (6 x 10 x 10)
__device__ float  g_norm [40];           // per-used-row squared norms
__device__ float  g_G    [64];           // W_c W_c^T (8x8)
__device__ float  g_v    [8];            // W_c . b_c
__device__ float  g_n0   [1];            // ||b_c||^2
__device__ float2 g_rs   [128 * 48 * 48];// per-pair (combo-as-int-bits, rs_p)
__device__ __half g_Th   [10000 * 256];  // fp16 LN-applied cate row per combo (+bias)

// ---- per-lane loads ----
__device__ __forceinline__ void ld8(const float* __restrict__ p, int lane, U64 v[4]) {
    float4 a = __ldg((const float4*)p + lane);
    float4 b = __ldg((const float4*)p + 32 + lane);
    v[0] = f2pk(a.x, a.y); v[1] = f2pk(a.z, a.w);
    v[2] = f2pk(b.x, b.y); v[3] = f2pk(b.z, b.w);
}
__device__ __forceinline__ void ld4(const float* __restrict__ p, int dbase, U64 v[2]) {
    float4 a = __ldg((const float4*)(p + dbase));
    v[0] = f2pk(a.x, a.y); v[1] = f2pk(a.z, a.w);
}

// ===========================================================================
// K1: center rows of table_sc / W_sf / b_sf (makes LN means exactly 0)
// ===========================================================================
__global__ void __launch_bounds__(256) center_kernel(
    const float* __restrict__ tsc, const float* __restrict__ Wsf,
    const float* __restrict__ bsf)
{
    __shared__ float red[8];
    const int blk = blockIdx.x, t = threadIdx.x;
    const float* src; float* dst;
    if (blk < 44)      { src = tsc + blk * 256;        dst = g_tsc_c + blk * 256; }
    else if (blk < 52) { src = Wsf + (blk - 44) * 256; dst = g_wsf_c + (blk - 44) * 256; }
    else               { src = bsf;                    dst = g_bsf_c; }
    float v = __ldg(src + t);
    float s = warp_sum(v);
    if ((t & 31) == 0) red[t >> 5] = s;
    __syncthreads();
    float tot = 0.f;
#pragma unroll
    for (int k = 0; k < 8; k++) tot += red[k];
    dst[t] = v - tot * (1.0f / 256.0f);
}

// ===========================================================================
// K2: dots (blocks 0..89) + prep2 (blocks 90..98)
// ===========================================================================
__global__ void __launch_bounds__(256) dots_prep_kernel(const float* __restrict__ gsf)
{
    if (blockIdx.x >= 90) {
        const int blk = blockIdx.x - 90, t = threadIdx.x;
        const float gv = __ldg(gsf + t);
        if (blk < 8) g_wp[blk * 256 + t] = g_wsf_c[blk * 256 + t] * gv;
        else         g_bp[t]             = g_bsf_c[t] * gv;
        return;
    }
    const int job = blockIdx.x * 8 + (threadIdx.x >> 5);
    const int lane = threadIdx.x & 31;
    if (job >= 713) return;
    const float *v1, *v2; float* dst;
    if (job < 600) {
        int combo = job / 100, ij = job % 100, i = ij / 10, jj = ij % 10;
        int r1, r2;
        switch (combo) {
            case 0:  r1 = 1 + i;  r2 = 12 + jj; break;   // A,B
            case 1:  r1 = 23 + i; r2 = 34 + jj; break;   // C,D
            case 2:  r1 = 1 + i;  r2 = 23 + jj; break;   // A,C
            case 3:  r1 = 1 + i;  r2 = 34 + jj; break;   // A,D
            case 4:  r1 = 12 + i; r2 = 23 + jj; break;   // B,C
            default: r1 = 12 + i; r2 = 34 + jj; break;   // B,D
        }
        v1 = g_tsc_c + r1 * 256; v2 = g_tsc_c + r2 * 256; dst = g_dotc + job;
    } else if (job < 640) {
        int jn = job - 600;
        int row = (jn / 10) * 11 + 1 + (jn % 10);
        v1 = v2 = g_tsc_c + row * 256; dst = g_norm + jn;
    } else if (job < 704) {
        int i = (job - 640) >> 3, jj = (job - 640) & 7;
        v1 = g_wsf_c + i * 256; v2 = g_wsf_c + jj * 256; dst = g_G + (job - 640);
    } else if (job < 712) {
        v1 = g_wsf_c + (job - 704) * 256; v2 = g_bsf_c; dst = g_v + (job - 704);
    } else {
        v1 = v2 = g_bsf_c; dst = g_n0;
    }
    float s = 0.f;
#pragma unroll
    for (int k = lane; k < 256; k += 32) s += v1[k] * v2[k];
    s = warp_sum(s);
    if (lane == 0) *dst = s;
}

// ===========================================================================
// K3: tbl (blocks 0..499) + rs_ve (blocks 500..1651)
// ===========================================================================
__global__ void __launch_bounds__(256) prep_main_kernel(
    const float* __restrict__ gsc_p, const float* __restrict__ bsc_p,
    const float* __restrict__ bsf_ln,
    const int4* __restrict__ sfc, const float4* __restrict__ sff,
    const float4* __restrict__ vev, float4* __restrict__ out)
{
    const int t = threadIdx.x;

    if (blockIdx.x < 500) {
        // ----------------- tbl: per-combo fp16 table -----------------
        __shared__ float sQ[600];
        for (int idx = t; idx < 600; idx += 256) {
            float val = g_dotc[idx] * 2.f;
            int combo = idx / 100, ij = idx % 100, i = ij / 10, jj = ij % 10;
            if (combo == 0)      val += g_norm[i]      + g_norm[10 + jj];
            else if (combo == 1) val += g_norm[20 + i] + g_norm[30 + jj];
            sQ[idx] = val;
        }
        __syncthreads();

        const int lane = t & 31;
        const int job = blockIdx.x * 8 + (t >> 5);      // 0..3999
        const int triple = job >> 2;                     // 0..999
        const int dh  = (job >> 1) & 1;
        const int ddh = job & 1;
        const int a  = triple / 100;
        const int bb = (triple / 10) % 10;
        const int cc = triple % 10;
        const int dbase = dh * 128 + lane * 4;

        const float base = sQ[a * 10 + bb] + sQ[200 + a * 10 + cc] + sQ[400 + bb * 10 + cc];

        U64 gsc[2], bsum[2];
        ld4(gsc_p, dbase, gsc);
        {
            U64 t1[2], t2[2];
            ld4(bsc_p, dbase, t1);
            ld4(bsf_ln, dbase, t2);
            bsum[0] = f2add(t1[0], t2[0]);
            bsum[1] = f2add(t1[1], t2[1]);
        }

        U64 s3[2], u0[2], u1[2];
        ld4(g_tsc_c + (a + 1)   * 256, dbase, s3);
        ld4(g_tsc_c + (bb + 12) * 256, dbase, u0);
        ld4(g_tsc_c + (cc + 23) * 256, dbase, u1);
        s3[0] = f2add(s3[0], f2add(u0[0], u1[0]));
        s3[1] = f2add(s3[1], f2add(u0[1], u1[1]));

        __half* dst = g_Th + (size_t)triple * 10 * 256 + (5 * ddh) * 256 + dbase;
        const float* q1 = sQ + 100 + cc * 10;
        const float* q3 = sQ + 300 + a * 10;
        const float* q5 = sQ + 500 + bb * 10;

#pragma unroll
        for (int k = 0; k < 5; k++) {
            const int dd = 5 * ddh + k;
            U64 d2v[2];
            ld4(g_tsc_c + (dd + 34) * 256, dbase, d2v);
            const float sc = base + q1[dd] + q3[dd] + q5[dd];
            const float rs_c = rsqrtf(fmaf(sc, 1.0f / 256.0f, 1e-5f));
            const U64 rc = f2dup(rs_c);

            U64 o0 = f2fma(f2add(s3[0], d2v[0]), f2mul(gsc[0], rc), bsum[0]);
            U64 o1 = f2fma(f2add(s3[1], d2v[1]), f2mul(gsc[1], rc), bsum[1]);
            float a0, a1, b0, b1;
            f2un(o0, a0, a1); f2un(o1, b0, b1);
            __half2 h0 = __floats2half2_rn(a0, a1);
            __half2 h1 = __floats2half2_rn(b0, b1);
            uint2 w;
            w.x = *(unsigned*)&h0;
            w.y = *(unsigned*)&h1;
            *(uint2*)dst = w;
            dst += 256;
        }
        return;
    }

    // ----------------- rs_ve: per-pair meta + virtual-edge border -----------------
    __shared__ float sG[64], sv2[8];
    __shared__ float sn0;
    if (t < 64) sG[t] = g_G[t];
    if (t < 8)  sv2[t] = 2.f * g_v[t];
    if (t == 0) sn0 = g_n0[0];
    __syncthreads();

    const int blk = blockIdx.x - 500;                  // 0..1151
    const int NB = 1152;
    const int TOT = 128 * 48 * 48;
    for (int q = blk * 256 + t; q < TOT; q += NB * 256) {
        const int4   ci = __ldg(sfc + q);
        const float4 x0 = __ldg(sff + 2 * q);
        const float4 x1 = __ldg(sff + 2 * q + 1);
        const int combo = ((ci.x * 10 + ci.y) * 10 + ci.z) * 10 + ci.w;
        const float xv[8] = { x0.x, x0.y, x0.z, x0.w, x1.x, x1.y, x1.z, x1.w };
        float sp = sn0;
#pragma unroll
        for (int a = 0; a < 8; a++) {
            float y = sv2[a];
#pragma unroll
            for (int b = 0; b < 8; b++) y = fmaf(sG[a * 8 + b], xv[b], y);
            sp = fmaf(xv[a], y, sp);
        }
        float2 meta;
        meta.x = __int_as_float(combo);
        meta.y = rsqrtf(fmaf(sp, 1.0f / 256.0f, 1e-5f));
        g_rs[q] = meta;
    }

    const int vtot = 128 * 97 * 64;
    for (int v = blk * 256 + t; v < vtot; v += NB * 256) {
        int d4 = v & 63;
        int r = v >> 6;
        int b = r / 97;
        int pos = r - b * 97;                  // 0..48: (0,j)   49..96: (i,0)
        size_t cell = (size_t)b * 2401 + (pos < 49 ? pos : (size_t)(pos - 48) * 49);
        out[cell * 64 + d4] = __ldg(vev + d4);
    }
}

// ===========================================================================
// K4 (PROFILED SLOT): interior fill — warp per pair, fp16 T, streaming stores.
// ===========================================================================
__global__ void __launch_bounds__(128, 4) fill_kernel(
    const float4* __restrict__ sff,   // [B*48*48*2] float4
    float* __restrict__ out)
{
    const int lane = threadIdx.x & 31;
    const int warp = threadIdx.x >> 5;

    U64 wp[8][4], bp[4];
#pragma unroll
    for (int f = 0; f < 8; f++) ld8(g_wp + f * 256, lane, wp[f]);
    ld8(g_bp, lane, bp);

    const int TOT = 128 * 48 * 48;
    const int NW = gridDim.x * 4;
    const int gw = blockIdx.x * 4 + warp;
    const int chunk = (TOT + NW - 1) / NW;
    int q = gw * chunk;
    int qend = q + chunk; if (qend > TOT) qend = TOT;
    if (q >= qend) return;

    int b = q / 2304;
    int rem = q - b * 2304;
    int i = rem / 48;
    int j = rem - i * 48;
    float* dst = out + ((size_t)((b * 49 + i + 1) * 49 + (j + 1))) * 256 + lane * 4;
    const int lane4 = lane * 4;

    while (q < qend) {
        const float2 meta = __ldg((const float2*)g_rs + q);
        const int combo = __float_as_int(meta.x);
        const float4 x0 = __ldg(sff + 2 * q);
        const float4 x1 = __ldg(sff + 2 * q + 1);

        const __half* Tr = g_Th + (size_t)combo * 256 + lane4;
        const uint2 ta = __ldg((const uint2*)Tr);          // halves 4L..4L+3
        const uint2 tb = __ldg((const uint2*)(Tr + 128));  // halves 128+4L..

        U64 p0 = bp[0], p1 = bp[1], p2 = bp[2], p3 = bp[3];
        const float xv[8] = { x0.x, x0.y, x0.z, x0.w, x1.x, x1.y, x1.z, x1.w };
#pragma unroll
        for (int f = 0; f < 8; f++) {
            U64 xd = f2dup(xv[f]);
            p0 = f2fma(wp[f][0], xd, p0);
            p1 = f2fma(wp[f][1], xd, p1);
            p2 = f2fma(wp[f][2], xd, p2);
            p3 = f2fma(wp[f][3], xd, p3);
        }

        const float2 f0 = __half22float2(*(const __half2*)&ta.x);
        const float2 f1 = __half22float2(*(const __half2*)&ta.y);
        const float2 f2_ = __half22float2(*(const __half2*)&tb.x);
        const float2 f3 = __half22float2(*(const __half2*)&tb.y);

        const U64 rp = f2dup(meta.y);
        U64 o0 = f2fma(p0, rp, f2pk(f0.x, f0.y));
        U64 o1 = f2fma(p1, rp, f2pk(f1.x, f1.y));
        U64 o2 = f2fma(p2, rp, f2pk(f2_.x, f2_.y));
        U64 o3 = f2fma(p3, rp, f2pk(f3.x, f3.y));

        stcs2(dst,       o0, o1);
        stcs2(dst + 128, o2, o3);

        q++;
        dst += 256;
        if (++j == 48) {
            j = 0; dst += 256;
            if (++i == 48) { i = 0; dst += 49 * 256; }
        }
    }
}

// ===========================================================================
// K5: per-bond embedding hb — warp per 2 bonds (grid 512 x 256)
// ===========================================================================
__global__ void __launch_bounds__(256) hb_kernel(
    const int*   __restrict__ bfc,   // [B,E,3]
    const float* __restrict__ bff,   // [B,E,4]
    const float* __restrict__ mask,  // [B,E]
    const float* __restrict__ tbc,   // [33,256]
    const float* __restrict__ g1p, const float* __restrict__ b1p,
    const float* __restrict__ Wbf,   // [4,256]
    const float* __restrict__ bbf,
    const float* __restrict__ g2p, const float* __restrict__ b2p)
{
    const int lane = threadIdx.x & 31;
    const int gw = blockIdx.x * 8 + (threadIdx.x >> 5);   // 0..4095
    const int be0 = gw * 2;

    U64 g1[4], b1[4], g2[4], b2[4], bb[4], w[4][4];
    ld8(g1p, lane, g1); ld8(b1p, lane, b1);
    ld8(g2p, lane, g2); ld8(b2p, lane, b2);
    ld8(bbf, lane, bb);
#pragma unroll
    for (int f = 0; f < 4; f++) ld8(Wbf + f * 256, lane, w[f]);

#pragma unroll
    for (int u = 0; u < 2; u++) {
        const int be = be0 + u;
        const int c0 = __ldg(bfc + be * 3 + 0) + 1;
        const int c1 = __ldg(bfc + be * 3 + 1) + 12;
        const int c2 = __ldg(bfc + be * 3 + 2) + 23;

        U64 xc[4], t0[4], t1[4];
        ld8(tbc + c0 * 256, lane, xc);
        ld8(tbc + c1 * 256, lane, t0);
        ld8(tbc + c2 * 256, lane, t1);
#pragma unroll
        for (int k = 0; k < 4; k++) xc[k] = f2add(xc[k], f2add(t0[k], t1[k]));

        const float4 xf = __ldg((const float4*)(bff + be * 4));
        U64 xp[4];
#pragma unroll
        for (int k = 0; k < 4; k++) xp[k] = bb[k];
        {
            U64 d0 = f2dup(xf.x), d1 = f2dup(xf.y), d2 = f2dup(xf.z), d3 = f2dup(xf.w);
#pragma unroll
            for (int k = 0; k < 4; k++) {
                xp[k] = f2fma(w[0][k], d0, xp[k]);
                xp[k] = f2fma(w[1][k], d1, xp[k]);
                xp[k] = f2fma(w[2][k], d2, xp[k]);
                xp[k] = f2fma(w[3][k], d3, xp[k]);
            }
        }

        U64 sC = f2add(f2add(xc[0], xc[1]), f2add(xc[2], xc[3]));
        U64 qC = f2fma(xc[0], xc[0], f2fma(xc[1], xc[1], f2fma(xc[2], xc[2], f2mul(xc[3], xc[3]))));
        U64 sP = f2add(f2add(xp[0], xp[1]), f2add(xp[2], xp[3]));
        U64 qP = f2fma(xp[0], xp[0], f2fma(xp[1], xp[1], f2fma(xp[2], xp[2], f2mul(xp[3], xp[3]))));
        float a0, a1, s_c, q_c, s_p, q_p;
        f2un(sC, a0, a1); s_c = a0 + a1;
        f2un(qC, a0, a1); q_c = a0 + a1;
        f2un(sP, a0, a1); s_p = a0 + a1;
        f2un(qP, a0, a1); q_p = a0 + a1;
#pragma unroll
        for (int o = 16; o; o >>= 1) {
            s_c += __shfl_xor_sync(0xffffffffu, s_c, o);
            q_c += __shfl_xor_sync(0xffffffffu, q_c, o);
            s_p += __shfl_xor_sync(0xffffffffu, s_p, o);
            q_p += __shfl_xor_sync(0xffffffffu, q_p, o);
        }
        const float muC = s_c * (1.0f / 256.0f);
        const float rsC = rsqrtf(fmaf(q_c, 1.0f / 256.0f, -muC * muC) + 1e-5f);
        const float muP = s_p * (1.0f / 256.0f);
        const float rsP = rsqrtf(fmaf(q_p, 1.0f / 256.0f, -muP * muP) + 1e-5f);

        const float mv = __ldg(mask + be);
        const U64 mk = f2dup(mv);
        const U64 nmC = f2dup(-muC), rC = f2dup(rsC);
        const U64 nmP = f2dup(-muP), rP = f2dup(rsP);

        float* dst = g_hb + be * 256 + lane * 4;
#pragma unroll
        for (int half = 0; half < 2; half++) {
            U64 rgC0 = f2mul(g1[2 * half], rC),     rgC1 = f2mul(g1[2 * half + 1], rC);
            U64 kC0  = f2fma(rgC0, nmC, b1[2 * half]), kC1 = f2fma(rgC1, nmC, b1[2 * half + 1]);
            U64 rgP0 = f2mul(g2[2 * half], rP),     rgP1 = f2mul(g2[2 * half + 1], rP);
            U64 kP0  = f2fma(rgP0, nmP, b2[2 * half]), kP1 = f2fma(rgP1, nmP, b2[2 * half + 1]);
            U64 o0 = f2add(f2fma(xc[2 * half], rgC0, kC0), f2fma(xp[2 * half], rgP0, kP0));
            U64 o1 = f2add(f2fma(xc[2 * half + 1], rgC1, kC1), f2fma(xp[2 * half + 1], rgP1, kP1));
            o0 = f2mul(o0, mk); o1 = f2mul(o1, mk);
            ulonglong2 wv; wv.x = o0; wv.y = o1;
            *(ulonglong2*)(dst + half * 128) = wv;
        }
    }
}

// ===========================================================================
// K6: g_rev = g_hb @ W_rev + b_rev   (8192x256 @ 256x256)
// ===========================================================================
__global__ void __launch_bounds__(256) rev_kernel(
    const float* __restrict__ Wrev,
    const float* __restrict__ brev)
{
    constexpr int RROWS = 16, RPAD = 20;
    __shared__ __align__(16) float As[256 * RPAD];

    const int row0 = blockIdx.x * RROWS;
    const int t = threadIdx.x;

    for (int idx = t; idx < 256 * RROWS; idx += 256) {
        int r = idx >> 8;
        int k = idx & 255;
        As[k * RPAD + r] = g_hb[(row0 + r) * 256 + k];
    }
    __syncthreads();

    U64 acc[8];
#pragma unroll
    for (int p = 0; p < 8; p++) acc[p] = 0ULL;

#pragma unroll 4
    for (int k = 0; k < 256; k++) {
        U64 wd = f2dup(__ldg(Wrev + k * 256 + t));
        const ulonglong2* ap = (const ulonglong2*)(As + k * RPAD);
#pragma unroll
        for (int q = 0; q < 4; q++) {
            ulonglong2 a = ap[q];
            acc[2 * q]     = f2fma(a.x, wd, acc[2 * q]);
            acc[2 * q + 1] = f2fma(a.y, wd, acc[2 * q + 1]);
        }
    }

    const float bv = __ldg(brev + t);
#pragma unroll
    for (int p = 0; p < 8; p++) {
        float lo, hi; f2un(acc[p], lo, hi);
        g_rev[(row0 + 2 * p)     * 256 + t] = lo + bv;
        g_rev[(row0 + 2 * p + 1) * 256 + t] = hi + bv;
    }
}

// ===========================================================================
// K7: scatter-add bonds with vectorized red.global (v4.f32)
// ===========================================================================
__global__ void __launch_bounds__(128) scatter_kernel(
    const int* __restrict__ bidx,
    float* __restrict__ out)
{
    const int be = blockIdx.x;
    const int b = be >> 6, e = be & 63;
    const int t = threadIdx.x;
    const int d4 = t & 63;
    const bool fwd = t < 64;

    const int i0 = __ldg(bidx + (b * 2)     * 64 + e) + 1;
    const int i1 = __ldg(bidx + (b * 2 + 1) * 64 + e) + 1;

    const float4* src = (const float4*)(fwd ? g_hb : g_rev) + be * 64 + d4;
    const float4 v = *src;

    const size_t cell = fwd ? ((size_t)(b * 49 + i0) * 49 + i1)
                            : ((size_t)(b * 49 + i1) * 49 + i0);
    float* p = out + cell * 256 + d4 * 4;
    asm volatile("red.global.add.v4.f32 [%0], {%1, %2, %3, %4};"
                 :: "l"(p), "f"(v.x), "f"(v.y), "f"(v.z), "f"(v.w)
                 : "memory");
}

// ===========================================================================
extern "C" void kernel_launch(void* const* d_in, const int* in_sizes, int n_in,
                              void* d_out, int out_size)
{
    (void)in_sizes; (void)n_in; (void)out_size;

    const int*    bond_index = (const int*)   d_in[0];
    const int*    bfc        = (const int*)   d_in[1];
    const float*  bff        = (const float*) d_in[2];
    const float*  bmask      = (const float*) d_in[3];
    const int4*   sfc        = (const int4*)  d_in[4];
    const float4* sff        = (const float4*)d_in[5];
    const float*  tbc        = (const float*) d_in[6];
    const float*  ln_bc_g    = (const float*) d_in[7];
    const float*  ln_bc_b    = (const float*) d_in[8];
    const float*  W_bf       = (const float*) d_in[9];
    const float*  b_bf       = (const float*) d_in[10];
    const float*  ln_bf_g    = (const float*) d_in[11];
    const float*  ln_bf_b    = (const float*) d_in[12];
    const float*  tsc        = (const float*) d_in[13];
    const float*  ln_sc_g    = (const float*) d_in[14];
    const float*  ln_sc_b    = (const float*) d_in[15];
    const float*  W_sf       = (const float*) d_in[16];
    const float*  b_sf       = (const float*) d_in[17];
    const float*  ln_sf_g    = (const float*) d_in[18];
    const float*  ln_sf_b    = (const float*) d_in[19];
    const float*  ve         = (const float*) d_in[20];
    const float*  W_rev      = (const float*) d_in[21];
    const float*  b_rev      = (const float*) d_in[22];
    float* out = (float*)d_out;

    center_kernel<<<53, 256>>>(tsc, W_sf, b_sf);
    dots_prep_kernel<<<99, 256>>>(ln_sf_g);
    prep_main_kernel<<<1652, 256>>>(ln_sc_g, ln_sc_b, ln_sf_b,
                                    sfc, sff, (const float4*)ve, (float4*)out);
    fill_kernel<<<592, 128>>>(sff, out);
    hb_kernel<<<512, 256>>>(bfc, bff, bmask, tbc, ln_bc_g, ln_bc_b,
                            W_bf, b_bf, ln_bf_g, ln_bf_b);
    rev_kernel<<<512, 256>>>(W_rev, b_rev);
    scatter_kernel<<<8192, 128>>>(bond_index, out);
}